// round 1
// baseline (speedup 1.0000x reference)
#include <cuda_runtime.h>

#define BATCH 8
#define TLEN 4096
#define INDIM 128
#define OUTDIM 128
#define HID 256

// ---- scratch (device globals: allocation-free rule) ----
__device__ float g_lam_re[HID];
__device__ float g_lam_im[HID];
__device__ float g_gamma[HID];
__device__ float g_mag[HID];
__device__ float g_th[HID];
__device__ float g_bx_re[(size_t)BATCH * HID * TLEN];
__device__ float g_bx_im[(size_t)BATCH * HID * TLEN];

// ---------------------------------------------------------------------------
// Kernel 0: per-channel recurrence parameters
// ---------------------------------------------------------------------------
__global__ void params_kernel(const float* __restrict__ nu_log,
                              const float* __restrict__ theta_log) {
    int h = threadIdx.x;
    if (h < HID) {
        float mag = expf(-expf(nu_log[h]));
        float th  = expf(theta_log[h]);
        g_mag[h] = mag;
        g_th[h]  = th;
        g_lam_re[h] = mag * cosf(th);
        g_lam_im[h] = mag * sinf(th);
        g_gamma[h]  = sqrtf(fmaxf(1.0f - mag * mag, 0.0f));
    }
}

// ---------------------------------------------------------------------------
// Kernel 1: BX[b,h,t] = gamma[h] * (X[b,t,:] . B_re[h,:],  X[b,t,:] . B_im[h,:])
// Block: 64 t x 64 h tile, K-chunks of 32. 256 threads, 4x4 micro-tile.
// Output layout [b][h][t] (t contiguous) for the scan.
// ---------------------------------------------------------------------------
__global__ __launch_bounds__(256)
void gemm1_kernel(const float* __restrict__ X,
                  const float* __restrict__ Bre,
                  const float* __restrict__ Bim) {
    __shared__ float s_x [32][65];   // [k][t]
    __shared__ float s_br[32][65];   // [k][h]
    __shared__ float s_bi[32][65];   // [k][h]

    int b  = blockIdx.z;
    int t0 = blockIdx.x * 64;
    int h0 = blockIdx.y * 64;
    int tid = threadIdx.x;
    int tx = tid & 15;          // t: t_local = tx + 16*i
    int ty = tid >> 4;          // h: h_local = ty*4 + j

    float acc_re[4][4];
    float acc_im[4][4];
#pragma unroll
    for (int j = 0; j < 4; j++)
#pragma unroll
        for (int i = 0; i < 4; i++) { acc_re[j][i] = 0.f; acc_im[j][i] = 0.f; }

    for (int k0 = 0; k0 < INDIM; k0 += 32) {
        // X tile: 64t x 32k -> s_x[k][t]
        for (int l = tid; l < 64 * 32; l += 256) {
            int t = l >> 5;
            int k = l & 31;
            s_x[k][t] = X[((size_t)b * TLEN + (t0 + t)) * INDIM + k0 + k];
        }
        // B tiles: 64h x 32k -> s_b*[k][h]
        for (int l = tid; l < 64 * 32; l += 256) {
            int h = l >> 5;
            int k = l & 31;
            s_br[k][h] = Bre[(size_t)(h0 + h) * INDIM + k0 + k];
            s_bi[k][h] = Bim[(size_t)(h0 + h) * INDIM + k0 + k];
        }
        __syncthreads();

#pragma unroll
        for (int k = 0; k < 32; k++) {
            float xv[4], br[4], bi[4];
#pragma unroll
            for (int i = 0; i < 4; i++) xv[i] = s_x[k][tx + 16 * i];
#pragma unroll
            for (int j = 0; j < 4; j++) {
                br[j] = s_br[k][ty * 4 + j];
                bi[j] = s_bi[k][ty * 4 + j];
            }
#pragma unroll
            for (int j = 0; j < 4; j++)
#pragma unroll
                for (int i = 0; i < 4; i++) {
                    acc_re[j][i] += xv[i] * br[j];
                    acc_im[j][i] += xv[i] * bi[j];
                }
        }
        __syncthreads();
    }

#pragma unroll
    for (int j = 0; j < 4; j++) {
        int h = h0 + ty * 4 + j;
        float gam = g_gamma[h];
        size_t base = ((size_t)b * HID + h) * TLEN + t0;
#pragma unroll
        for (int i = 0; i < 4; i++) {
            int t = tx + 16 * i;
            g_bx_re[base + t] = gam * acc_re[j][i];
            g_bx_im[base + t] = gam * acc_im[j][i];
        }
    }
}

// ---------------------------------------------------------------------------
// Kernel 2: inclusive complex scan over t, in place on g_bx.
// One warp per (b,h). lambda is constant per h, so the Kogge-Stone scan
// only needs lam^{1,2,4,8,16}; the cross-chunk carry uses lam^{lane+1}.
// ---------------------------------------------------------------------------
__global__ __launch_bounds__(256)
void scan_kernel() {
    int wg   = (blockIdx.x * blockDim.x + threadIdx.x) >> 5;
    int lane = threadIdx.x & 31;
    if (wg >= BATCH * HID) return;
    int b = wg >> 8;      // / HID
    int h = wg & (HID - 1);

    float lre = g_lam_re[h], lim = g_lam_im[h];

    // lam^(2^s), s = 0..4
    float pdre[5], pdim[5];
    {
        float pr = lre, pi = lim;
        pdre[0] = pr; pdim[0] = pi;
#pragma unroll
        for (int s = 1; s < 5; s++) {
            float nr = pr * pr - pi * pi;
            float ni = 2.f * pr * pi;
            pdre[s] = nr; pdim[s] = ni;
            pr = nr; pi = ni;
        }
    }
    // lam^(lane+1) for carry application
    float mag = g_mag[h], th = g_th[h];
    float mp  = powf(mag, (float)(lane + 1));
    float sa, ca;
    sincosf(th * (float)(lane + 1), &sa, &ca);
    float cpre = mp * ca, cpim = mp * sa;

    float carry_re = 0.f, carry_im = 0.f;
    size_t base = ((size_t)b * HID + h) * TLEN;

    // double-buffered loads to hide DRAM latency behind the dependent carry
    float nxr = g_bx_re[base + lane];
    float nxi = g_bx_im[base + lane];

    for (int c = 0; c < TLEN / 32; c++) {
        float xr = nxr, xi = nxi;
        if (c + 1 < TLEN / 32) {
            nxr = g_bx_re[base + (c + 1) * 32 + lane];
            nxi = g_bx_im[base + (c + 1) * 32 + lane];
        }
#pragma unroll
        for (int s = 0; s < 5; s++) {
            int d = 1 << s;
            float yr = __shfl_up_sync(0xffffffffu, xr, d);
            float yi = __shfl_up_sync(0xffffffffu, xi, d);
            if (lane >= d) {
                xr += pdre[s] * yr - pdim[s] * yi;
                xi += pdre[s] * yi + pdim[s] * yr;
            }
        }
        // apply carry from previous chunk: x += lam^(lane+1) * carry
        xr += cpre * carry_re - cpim * carry_im;
        xi += cpre * carry_im + cpim * carry_re;

        g_bx_re[base + c * 32 + lane] = xr;
        g_bx_im[base + c * 32 + lane] = xi;

        carry_re = __shfl_sync(0xffffffffu, xr, 31);
        carry_im = __shfl_sync(0xffffffffu, xi, 31);
    }
}

// ---------------------------------------------------------------------------
// Kernel 3: Y[b,t,o] = sum_h (h_re*C_re[o,h] - h_im*C_im[o,h]) + sum_i X*D[o,i]
// Block: 64 t x 128 o tile, 256 threads, 4t x 8o micro-tile (o = tx + 16*j).
// ---------------------------------------------------------------------------
__global__ __launch_bounds__(256)
void gemm2_kernel(const float* __restrict__ X,
                  const float* __restrict__ Cre,
                  const float* __restrict__ Cim,
                  const float* __restrict__ Dm,
                  float* __restrict__ Y) {
    __shared__ float s_a [64][17];    // hiddens re / X  [t][kc]
    __shared__ float s_b [64][17];    // hiddens im      [t][kc]
    __shared__ float s_wr[128][17];   // C_re / D        [o][kc]
    __shared__ float s_wi[128][17];   // C_im            [o][kc]

    int b  = blockIdx.y;
    int t0 = blockIdx.x * 64;
    int tid = threadIdx.x;
    int tx = tid & 15;    // o = tx + 16*j
    int ty = tid >> 4;    // t = ty*4 + i

    float acc[4][8];
#pragma unroll
    for (int i = 0; i < 4; i++)
#pragma unroll
        for (int j = 0; j < 8; j++) acc[i][j] = 0.f;

    // ---- phase 1: complex C projection, K = HID (chunks of 16) ----
    for (int h0 = 0; h0 < HID; h0 += 16) {
        for (int l = tid; l < 64 * 16; l += 256) {
            int hc = l >> 6;
            int t  = l & 63;
            size_t src = ((size_t)b * HID + (h0 + hc)) * TLEN + t0 + t;
            s_a[t][hc] = g_bx_re[src];
            s_b[t][hc] = g_bx_im[src];
        }
        for (int l = tid; l < 128 * 16; l += 256) {
            int o  = l >> 4;
            int hc = l & 15;
            s_wr[o][hc] = Cre[(size_t)o * HID + h0 + hc];
            s_wi[o][hc] = Cim[(size_t)o * HID + h0 + hc];
        }
        __syncthreads();

#pragma unroll
        for (int hc = 0; hc < 16; hc++) {
            float hr[4], hi[4], wr[8], wi[8];
#pragma unroll
            for (int i = 0; i < 4; i++) {
                hr[i] = s_a[ty * 4 + i][hc];
                hi[i] = s_b[ty * 4 + i][hc];
            }
#pragma unroll
            for (int j = 0; j < 8; j++) {
                int o = tx + 16 * j;
                wr[j] = s_wr[o][hc];
                wi[j] = s_wi[o][hc];
            }
#pragma unroll
            for (int i = 0; i < 4; i++)
#pragma unroll
                for (int j = 0; j < 8; j++) {
                    acc[i][j] += hr[i] * wr[j] - hi[i] * wi[j];
                }
        }
        __syncthreads();
    }

    // ---- phase 2: D term, K = INDIM (chunks of 16) ----
    for (int i0 = 0; i0 < INDIM; i0 += 16) {
        for (int l = tid; l < 64 * 16; l += 256) {
            int t  = l >> 4;
            int ic = l & 15;
            s_a[t][ic] = X[((size_t)b * TLEN + t0 + t) * INDIM + i0 + ic];
        }
        for (int l = tid; l < 128 * 16; l += 256) {
            int o  = l >> 4;
            int ic = l & 15;
            s_wr[o][ic] = Dm[(size_t)o * INDIM + i0 + ic];
        }
        __syncthreads();

#pragma unroll
        for (int ic = 0; ic < 16; ic++) {
            float xv[4], dv[8];
#pragma unroll
            for (int i = 0; i < 4; i++) xv[i] = s_a[ty * 4 + i][ic];
#pragma unroll
            for (int j = 0; j < 8; j++) dv[j] = s_wr[tx + 16 * j][ic];
#pragma unroll
            for (int i = 0; i < 4; i++)
#pragma unroll
                for (int j = 0; j < 8; j++) acc[i][j] += xv[i] * dv[j];
        }
        __syncthreads();
    }

    // ---- store ----
#pragma unroll
    for (int i = 0; i < 4; i++) {
        size_t yb = ((size_t)b * TLEN + t0 + ty * 4 + i) * OUTDIM;
#pragma unroll
        for (int j = 0; j < 8; j++) {
            Y[yb + tx + 16 * j] = acc[i][j];
        }
    }
}

// ---------------------------------------------------------------------------
extern "C" void kernel_launch(void* const* d_in, const int* in_sizes, int n_in,
                              void* d_out, int out_size) {
    const float* X         = (const float*)d_in[0];
    const float* nu_log    = (const float*)d_in[1];
    const float* theta_log = (const float*)d_in[2];
    const float* B_re      = (const float*)d_in[3];
    const float* B_im      = (const float*)d_in[4];
    const float* C_re      = (const float*)d_in[5];
    const float* C_im      = (const float*)d_in[6];
    const float* D         = (const float*)d_in[7];
    float* Y = (float*)d_out;

    params_kernel<<<1, 256>>>(nu_log, theta_log);

    dim3 g1(TLEN / 64, HID / 64, BATCH);
    gemm1_kernel<<<g1, 256>>>(X, B_re, B_im);

    scan_kernel<<<(BATCH * HID * 32) / 256, 256>>>();

    dim3 g2(TLEN / 64, BATCH);
    gemm2_kernel<<<g2, 256>>>(X, C_re, C_im, D, Y);
}

// round 2
// speedup vs baseline: 1.1779x; 1.1779x over previous
#include <cuda_runtime.h>

#define BATCH 8
#define TLEN 4096
#define INDIM 128
#define OUTDIM 128
#define HID 256

typedef unsigned long long u64;

// ---- scratch (device globals: allocation-free rule) ----
__device__ float g_lam_re[HID];
__device__ float g_lam_im[HID];
__device__ float g_gamma[HID];
__device__ float g_mag[HID];
__device__ float g_th[HID];
__device__ float g_bx_re[(size_t)BATCH * HID * TLEN];
__device__ float g_bx_im[(size_t)BATCH * HID * TLEN];

// ---- packed f32x2 helpers ----
__device__ __forceinline__ u64 ffma2(u64 a, u64 b, u64 c) {
    u64 d;
    asm("fma.rn.f32x2 %0, %1, %2, %3;" : "=l"(d) : "l"(a), "l"(b), "l"(c));
    return d;
}
union F2U { float2 f; u64 u; };
__device__ __forceinline__ u64 pack2(float x, float y) {
    F2U v; v.f.x = x; v.f.y = y; return v.u;
}
__device__ __forceinline__ float2 unpack2(u64 a) {
    F2U v; v.u = a; return v.f;
}

// ---------------------------------------------------------------------------
// Kernel 0: per-channel recurrence parameters
// ---------------------------------------------------------------------------
__global__ void params_kernel(const float* __restrict__ nu_log,
                              const float* __restrict__ theta_log) {
    int h = threadIdx.x;
    if (h < HID) {
        float mag = expf(-expf(nu_log[h]));
        float th  = expf(theta_log[h]);
        g_mag[h] = mag;
        g_th[h]  = th;
        g_lam_re[h] = mag * cosf(th);
        g_lam_im[h] = mag * sinf(th);
        g_gamma[h]  = sqrtf(fmaxf(1.0f - mag * mag, 0.0f));
    }
}

// ---------------------------------------------------------------------------
// Kernel 1: BX[b,h,t] = gamma[h]*(X[b,t,:] . B_re[h,:], X[b,t,:] . B_im[h,:])
// 128t x 64h tile, 256 threads, micro 8t x 4h, f32x2 packed over t-pairs.
// Weights duplicated {w,w} in smem (pre-scaled by gamma) -> pure LDS.64+FFMA2.
// ---------------------------------------------------------------------------
#define G1_KC 16
__global__ __launch_bounds__(256)
void gemm1_kernel(const float* __restrict__ X,
                  const float* __restrict__ Bre,
                  const float* __restrict__ Bim) {
    __shared__ float s_x [G1_KC * 130];   // [k][t], t plain (128) + pad
    __shared__ float s_wr[G1_KC * 130];   // [k][2h] dup (128) + pad
    __shared__ float s_wi[G1_KC * 130];

    int b  = blockIdx.z;
    int t0 = blockIdx.x * 128;
    int h0 = blockIdx.y * 64;
    int tid = threadIdx.x;
    int tx = tid & 15;   // t-pair: t = 2*(tx+16*i) + {0,1}
    int ty = tid >> 4;   // h = ty + 16*j

    u64 acc_re[4][4], acc_im[4][4];
#pragma unroll
    for (int i = 0; i < 4; i++)
#pragma unroll
        for (int j = 0; j < 4; j++) { acc_re[i][j] = 0ull; acc_im[i][j] = 0ull; }

    for (int k0 = 0; k0 < INDIM; k0 += G1_KC) {
        // X tile: 128t x 16k, float4 loads, transposed store to s_x[k][t]
        {
            int f = tid;            // 256 threads x 2 float4 = 512
#pragma unroll
            for (int r = 0; r < 2; r++) {
                int t  = f >> 2;
                int kq = f & 3;
                const float4 v = *(const float4*)&X[((size_t)b * TLEN + t0 + t) * INDIM + k0 + kq * 4];
                s_x[(kq * 4 + 0) * 130 + t] = v.x;
                s_x[(kq * 4 + 1) * 130 + t] = v.y;
                s_x[(kq * 4 + 2) * 130 + t] = v.z;
                s_x[(kq * 4 + 3) * 130 + t] = v.w;
                f += 256;
            }
        }
        // B tiles: 64h x 16k, duplicated + gamma-scaled
        {
            int l = tid;            // 64*16 = 1024, 4 per thread
#pragma unroll
            for (int r = 0; r < 4; r++) {
                int h = l >> 4;
                int k = l & 15;
                float gam = g_gamma[h0 + h];
                float vr = gam * Bre[(size_t)(h0 + h) * INDIM + k0 + k];
                float vi = gam * Bim[(size_t)(h0 + h) * INDIM + k0 + k];
                *(u64*)&s_wr[k * 130 + 2 * h] = pack2(vr, vr);
                *(u64*)&s_wi[k * 130 + 2 * h] = pack2(vi, vi);
                l += 256;
            }
        }
        __syncthreads();

#pragma unroll
        for (int k = 0; k < G1_KC; k++) {
            u64 xt[4], br[4], bi[4];
#pragma unroll
            for (int i = 0; i < 4; i++)
                xt[i] = *(const u64*)&s_x[k * 130 + 2 * (tx + 16 * i)];
#pragma unroll
            for (int j = 0; j < 4; j++) {
                br[j] = *(const u64*)&s_wr[k * 130 + 2 * (ty + 16 * j)];
                bi[j] = *(const u64*)&s_wi[k * 130 + 2 * (ty + 16 * j)];
            }
#pragma unroll
            for (int i = 0; i < 4; i++)
#pragma unroll
                for (int j = 0; j < 4; j++) {
                    acc_re[i][j] = ffma2(xt[i], br[j], acc_re[i][j]);
                    acc_im[i][j] = ffma2(xt[i], bi[j], acc_im[i][j]);
                }
        }
        __syncthreads();
    }

    // store: BX[b][h][t], float2 over consecutive t
#pragma unroll
    for (int j = 0; j < 4; j++) {
        int h = h0 + ty + 16 * j;
        size_t base = ((size_t)b * HID + h) * TLEN + t0;
#pragma unroll
        for (int i = 0; i < 4; i++) {
            *(u64*)&g_bx_re[base + 2 * (tx + 16 * i)] = acc_re[i][j];
            *(u64*)&g_bx_im[base + 2 * (tx + 16 * i)] = acc_im[i][j];
        }
    }
}

// ---------------------------------------------------------------------------
// Kernel 2: inclusive complex scan over t, in place on g_bx.
// One warp per (b,h); Kogge-Stone with lam^{2^s}, carry via lam^{lane+1}.
// ---------------------------------------------------------------------------
__global__ __launch_bounds__(256)
void scan_kernel() {
    int wg   = (blockIdx.x * blockDim.x + threadIdx.x) >> 5;
    int lane = threadIdx.x & 31;
    if (wg >= BATCH * HID) return;
    int b = wg >> 8;
    int h = wg & (HID - 1);

    float lre = g_lam_re[h], lim = g_lam_im[h];
    float pdre[5], pdim[5];
    {
        float pr = lre, pi = lim;
        pdre[0] = pr; pdim[0] = pi;
#pragma unroll
        for (int s = 1; s < 5; s++) {
            float nr = pr * pr - pi * pi;
            float ni = 2.f * pr * pi;
            pdre[s] = nr; pdim[s] = ni;
            pr = nr; pi = ni;
        }
    }
    float mag = g_mag[h], th = g_th[h];
    float mp  = powf(mag, (float)(lane + 1));
    float sa, ca;
    sincosf(th * (float)(lane + 1), &sa, &ca);
    float cpre = mp * ca, cpim = mp * sa;

    float carry_re = 0.f, carry_im = 0.f;
    size_t base = ((size_t)b * HID + h) * TLEN;

    float nxr = g_bx_re[base + lane];
    float nxi = g_bx_im[base + lane];

    for (int c = 0; c < TLEN / 32; c++) {
        float xr = nxr, xi = nxi;
        if (c + 1 < TLEN / 32) {
            nxr = g_bx_re[base + (c + 1) * 32 + lane];
            nxi = g_bx_im[base + (c + 1) * 32 + lane];
        }
#pragma unroll
        for (int s = 0; s < 5; s++) {
            int d = 1 << s;
            float yr = __shfl_up_sync(0xffffffffu, xr, d);
            float yi = __shfl_up_sync(0xffffffffu, xi, d);
            if (lane >= d) {
                xr += pdre[s] * yr - pdim[s] * yi;
                xi += pdre[s] * yi + pdim[s] * yr;
            }
        }
        xr += cpre * carry_re - cpim * carry_im;
        xi += cpre * carry_im + cpim * carry_re;

        g_bx_re[base + c * 32 + lane] = xr;
        g_bx_im[base + c * 32 + lane] = xi;

        carry_re = __shfl_sync(0xffffffffu, xr, 31);
        carry_im = __shfl_sync(0xffffffffu, xi, 31);
    }
}

// ---------------------------------------------------------------------------
// Kernel 3: Y[b,t,o] = sum_h (h_re*C_re[o,h] - h_im*C_im[o,h]) + sum_i X*D[o,i]
// 128t x 128o tile, 256 threads, micro 8t x 8o, f32x2 packed over o-pairs.
// Hiddens duplicated {v,v} (im pre-negated) -> pure LDS.64 + FFMA2 inner loop.
// ---------------------------------------------------------------------------
#define G2_KC 8
__global__ __launch_bounds__(256)
void gemm2_kernel(const float* __restrict__ X,
                  const float* __restrict__ Cre,
                  const float* __restrict__ Cim,
                  const float* __restrict__ Dm,
                  float* __restrict__ Y) {
    __shared__ float s_a [G2_KC * 258];   // [kc][2t] dup re  (or X dup)
    __shared__ float s_b [G2_KC * 258];   // [kc][2t] dup -im
    __shared__ float s_wr[G2_KC * 130];   // [kc][o]  C_re / D
    __shared__ float s_wi[G2_KC * 130];   // [kc][o]  C_im

    int b  = blockIdx.y;
    int t0 = blockIdx.x * 128;
    int tid = threadIdx.x;
    int tx = tid & 15;    // o = 2*tx + 32*j + {0,1}
    int ty = tid >> 4;    // t = ty + 16*i

    u64 acc[8][4];
#pragma unroll
    for (int i = 0; i < 8; i++)
#pragma unroll
        for (int j = 0; j < 4; j++) acc[i][j] = 0ull;

    // ---- phase 1: complex C projection, K = HID, chunks of 8 ----
    for (int h0 = 0; h0 < HID; h0 += G2_KC) {
        {
            int idx = tid;           // 8*128 = 1024, 4 per thread
#pragma unroll
            for (int r = 0; r < 4; r++) {
                int hc = idx >> 7;
                int t  = idx & 127;
                size_t src = ((size_t)b * HID + h0 + hc) * TLEN + t0 + t;
                float re = g_bx_re[src];
                float im = g_bx_im[src];
                *(u64*)&s_a[hc * 258 + 2 * t] = pack2(re, re);
                *(u64*)&s_b[hc * 258 + 2 * t] = pack2(-im, -im);
                idx += 256;
            }
        }
        {
            int idx = tid;           // 128o * 8hc = 1024, 4 per thread
#pragma unroll
            for (int r = 0; r < 4; r++) {
                int o  = idx >> 3;
                int hc = idx & 7;
                s_wr[hc * 130 + o] = Cre[(size_t)o * HID + h0 + hc];
                s_wi[hc * 130 + o] = Cim[(size_t)o * HID + h0 + hc];
                idx += 256;
            }
        }
        __syncthreads();

#pragma unroll
        for (int hc = 0; hc < G2_KC; hc++) {
            u64 hr[8], hn[8], wr[4], wi[4];
#pragma unroll
            for (int i = 0; i < 8; i++) {
                hr[i] = *(const u64*)&s_a[hc * 258 + 2 * (ty + 16 * i)];
                hn[i] = *(const u64*)&s_b[hc * 258 + 2 * (ty + 16 * i)];
            }
#pragma unroll
            for (int j = 0; j < 4; j++) {
                wr[j] = *(const u64*)&s_wr[hc * 130 + 2 * tx + 32 * j];
                wi[j] = *(const u64*)&s_wi[hc * 130 + 2 * tx + 32 * j];
            }
#pragma unroll
            for (int i = 0; i < 8; i++)
#pragma unroll
                for (int j = 0; j < 4; j++) {
                    acc[i][j] = ffma2(hr[i], wr[j], acc[i][j]);
                    acc[i][j] = ffma2(hn[i], wi[j], acc[i][j]);
                }
        }
        __syncthreads();
    }

    // ---- phase 2: D term, K = INDIM, chunks of 8 ----
    for (int i0 = 0; i0 < INDIM; i0 += G2_KC) {
        {
            int idx = tid;           // 128t * 8ic
#pragma unroll
            for (int r = 0; r < 4; r++) {
                int t  = idx >> 3;
                int ic = idx & 7;
                float v = X[((size_t)b * TLEN + t0 + t) * INDIM + i0 + ic];
                *(u64*)&s_a[ic * 258 + 2 * t] = pack2(v, v);
                idx += 256;
            }
        }
        {
            int idx = tid;           // 128o * 8ic
#pragma unroll
            for (int r = 0; r < 4; r++) {
                int o  = idx >> 3;
                int ic = idx & 7;
                s_wr[ic * 130 + o] = Dm[(size_t)o * INDIM + i0 + ic];
                idx += 256;
            }
        }
        __syncthreads();

#pragma unroll
        for (int ic = 0; ic < G2_KC; ic++) {
            u64 xv[8], dv[4];
#pragma unroll
            for (int i = 0; i < 8; i++)
                xv[i] = *(const u64*)&s_a[ic * 258 + 2 * (ty + 16 * i)];
#pragma unroll
            for (int j = 0; j < 4; j++)
                dv[j] = *(const u64*)&s_wr[ic * 130 + 2 * tx + 32 * j];
#pragma unroll
            for (int i = 0; i < 8; i++)
#pragma unroll
                for (int j = 0; j < 4; j++)
                    acc[i][j] = ffma2(xv[i], dv[j], acc[i][j]);
        }
        __syncthreads();
    }

    // ---- store: float2 over consecutive o ----
#pragma unroll
    for (int i = 0; i < 8; i++) {
        size_t yb = ((size_t)b * TLEN + t0 + ty + 16 * i) * OUTDIM;
#pragma unroll
        for (int j = 0; j < 4; j++) {
            *(u64*)&Y[yb + 2 * tx + 32 * j] = acc[i][j];
        }
    }
}

// ---------------------------------------------------------------------------
extern "C" void kernel_launch(void* const* d_in, const int* in_sizes, int n_in,
                              void* d_out, int out_size) {
    const float* X         = (const float*)d_in[0];
    const float* nu_log    = (const float*)d_in[1];
    const float* theta_log = (const float*)d_in[2];
    const float* B_re      = (const float*)d_in[3];
    const float* B_im      = (const float*)d_in[4];
    const float* C_re      = (const float*)d_in[5];
    const float* C_im      = (const float*)d_in[6];
    const float* D         = (const float*)d_in[7];
    float* Y = (float*)d_out;

    params_kernel<<<1, 256>>>(nu_log, theta_log);

    dim3 g1(TLEN / 128, HID / 64, BATCH);
    gemm1_kernel<<<g1, 256>>>(X, B_re, B_im);

    scan_kernel<<<(BATCH * HID * 32) / 256, 256>>>();

    dim3 g2(TLEN / 128, BATCH);
    gemm2_kernel<<<g2, 256>>>(X, C_re, C_im, D, Y);
}

// round 3
// speedup vs baseline: 2.5880x; 2.1971x over previous
#include <cuda_runtime.h>
#include <cstdint>

#define BATCH 8
#define TLEN 4096
#define INDIM 128
#define OUTDIM 128
#define HID 256
#define PITCH 136

// ---- scratch (device globals: allocation-free rule) ----
__device__ float g_lam_re[HID];
__device__ float g_lam_im[HID];
__device__ float g_gamma[HID];
__device__ float g_mag[HID];
__device__ float g_th[HID];
__device__ float g_bx_re[(size_t)BATCH * HID * TLEN];    // [b][h][t]
__device__ float g_bx_im[(size_t)BATCH * HID * TLEN];
__device__ float g_xt[(size_t)BATCH * INDIM * TLEN];     // [b][i][t]
__device__ float g_wt2[640 * OUTDIM];                    // [k][o]: Cre^T | -Cim^T | D^T
__device__ float g_wg1[INDIM * 2 * HID];                 // [i][n]: n<256 gamma*Bre^T, else gamma*Bim^T

// ---- tf32 helpers ----
__device__ __forceinline__ float to_tf32(float x) {
    unsigned u;
    asm("cvt.rna.tf32.f32 %0, %1;" : "=r"(u) : "f"(x));
    return __uint_as_float(u);
}
__device__ __forceinline__ void mma8(float& d0, float& d1, float& d2, float& d3,
                                     float a0, float a1, float a2, float a3,
                                     float b0, float b1) {
    asm("mma.sync.aligned.m16n8k8.row.col.f32.tf32.tf32.f32 "
        "{%0,%1,%2,%3}, {%4,%5,%6,%7}, {%8,%9}, {%0,%1,%2,%3};"
        : "+f"(d0), "+f"(d1), "+f"(d2), "+f"(d3)
        : "r"(__float_as_uint(a0)), "r"(__float_as_uint(a1)),
          "r"(__float_as_uint(a2)), "r"(__float_as_uint(a3)),
          "r"(__float_as_uint(b0)), "r"(__float_as_uint(b1)));
}

// ---------------------------------------------------------------------------
// Kernel 0: per-channel recurrence parameters
// ---------------------------------------------------------------------------
__global__ void params_kernel(const float* __restrict__ nu_log,
                              const float* __restrict__ theta_log) {
    int h = threadIdx.x;
    if (h < HID) {
        float mag = expf(-expf(nu_log[h]));
        float th  = expf(theta_log[h]);
        g_mag[h] = mag;
        g_th[h]  = th;
        g_lam_re[h] = mag * cosf(th);
        g_lam_im[h] = mag * sinf(th);
        g_gamma[h]  = sqrtf(fmaxf(1.0f - mag * mag, 0.0f));
    }
}

// ---------------------------------------------------------------------------
// Prep: pack weight matrices (transposed, scaled/negated)
// ---------------------------------------------------------------------------
__global__ __launch_bounds__(256)
void prep_w_kernel(const float* __restrict__ Bre, const float* __restrict__ Bim,
                   const float* __restrict__ Cre, const float* __restrict__ Cim,
                   const float* __restrict__ Dm) {
    int idx = blockIdx.x * 256 + threadIdx.x;
    if (idx < 640 * OUTDIM) {
        int o = idx & 127;
        int k = idx >> 7;
        float v;
        if (k < 256)       v =  Cre[(size_t)o * HID + k];
        else if (k < 512)  v = -Cim[(size_t)o * HID + (k - 256)];
        else               v =  Dm[(size_t)o * INDIM + (k - 512)];
        g_wt2[k * OUTDIM + o] = v;
    } else {
        int j = idx - 640 * OUTDIM;
        if (j < INDIM * 2 * HID) {
            int n = j & 511;
            int i = j >> 9;
            int h = n & 255;
            float w = (n < 256) ? Bre[(size_t)h * INDIM + i] : Bim[(size_t)h * INDIM + i];
            g_wg1[i * 512 + n] = g_gamma[h] * w;
        }
    }
}

// ---------------------------------------------------------------------------
// Prep: transpose X -> g_xt[b][i][t]
// ---------------------------------------------------------------------------
__global__ __launch_bounds__(256)
void prep_xt_kernel(const float* __restrict__ X) {
    __shared__ float tile[32][33];
    int b  = blockIdx.z;
    int t0 = blockIdx.x * 32;
    int i0 = blockIdx.y * 32;
    int tid = threadIdx.x;
#pragma unroll
    for (int r = 0; r < 4; r++) {
        int idx = tid + 256 * r;
        int tl = idx >> 5, il = idx & 31;
        tile[tl][il] = X[((size_t)b * TLEN + t0 + tl) * INDIM + i0 + il];
    }
    __syncthreads();
#pragma unroll
    for (int r = 0; r < 4; r++) {
        int idx = tid + 256 * r;
        int il = idx >> 5, tl = idx & 31;
        g_xt[((size_t)b * INDIM + i0 + il) * TLEN + t0 + tl] = tile[tl][il];
    }
}

// ---------------------------------------------------------------------------
// GEMM1 (tf32 tensor): out[n][t] = sum_i g_xt[i][t] * Wg1[i][n]
// Block: 128 t x 128 n, 8 warps (2m x 4n), warp tile m64 n32.
// Writes g_bx_re (n<256) / g_bx_im (n>=256) in [b][h][t] layout.
// ---------------------------------------------------------------------------
__global__ __launch_bounds__(256)
void gemm1_kernel() {
    __shared__ float As[32 * PITCH];
    __shared__ float Ws[32 * PITCH];

    int tid = threadIdx.x, lane = tid & 31, wid = tid >> 5;
    int warp_m = wid >> 2, warp_n = wid & 3;
    int g = lane >> 2, tig = lane & 3;
    int b = blockIdx.z, t0 = blockIdx.x * 128, n0 = blockIdx.y * 128;

    float acc[4][4][4];
#pragma unroll
    for (int mi = 0; mi < 4; mi++)
#pragma unroll
        for (int ni = 0; ni < 4; ni++)
#pragma unroll
            for (int q = 0; q < 4; q++) acc[mi][ni][q] = 0.f;

    const int row = tid >> 3;
    const int cb  = tid & 7;

    for (int kc = 0; kc < INDIM; kc += 32) {
        const float* arow = g_xt + ((size_t)b * INDIM + kc + row) * TLEN + t0;
        const float* wrow = g_wg1 + (size_t)(kc + row) * 512 + n0;
#pragma unroll
        for (int r = 0; r < 4; r++) {
            int c = cb + 8 * r;
            float4 v = *(const float4*)(arow + 4 * c);
            float4 w;
            w.x = to_tf32(v.x); w.y = to_tf32(v.y); w.z = to_tf32(v.z); w.w = to_tf32(v.w);
            *(float4*)&As[row * PITCH + 4 * c] = w;
            float4 u = *(const float4*)(wrow + 4 * c);
            float4 s;
            s.x = to_tf32(u.x); s.y = to_tf32(u.y); s.z = to_tf32(u.z); s.w = to_tf32(u.w);
            *(float4*)&Ws[row * PITCH + 4 * c] = s;
        }
        __syncthreads();

#pragma unroll
        for (int ks = 0; ks < 4; ks++) {
            int k0r = (ks * 8 + tig) * PITCH;
            int k1r = k0r + 4 * PITCH;
            float a[4][4], bb[4][2];
#pragma unroll
            for (int mi = 0; mi < 4; mi++) {
                int m = warp_m * 64 + mi * 16 + g;
                a[mi][0] = As[k0r + m];
                a[mi][1] = As[k0r + m + 8];
                a[mi][2] = As[k1r + m];
                a[mi][3] = As[k1r + m + 8];
            }
#pragma unroll
            for (int ni = 0; ni < 4; ni++) {
                int n = warp_n * 32 + ni * 8 + g;
                bb[ni][0] = Ws[k0r + n];
                bb[ni][1] = Ws[k1r + n];
            }
#pragma unroll
            for (int mi = 0; mi < 4; mi++)
#pragma unroll
                for (int ni = 0; ni < 4; ni++)
                    mma8(acc[mi][ni][0], acc[mi][ni][1], acc[mi][ni][2], acc[mi][ni][3],
                         a[mi][0], a[mi][1], a[mi][2], a[mi][3],
                         bb[ni][0], bb[ni][1]);
        }
        __syncthreads();
    }

    // epilogue: scatter to [b][h][t]
#pragma unroll
    for (int ni = 0; ni < 4; ni++) {
        int n = n0 + warp_n * 32 + ni * 8 + 2 * tig;
        float* dst = (n < 256) ? g_bx_re : g_bx_im;
        int h = n & 255;
        size_t r0 = ((size_t)b * HID + h) * TLEN;
        size_t r1 = ((size_t)b * HID + h + 1) * TLEN;
#pragma unroll
        for (int mi = 0; mi < 4; mi++) {
            int t = t0 + warp_m * 64 + mi * 16 + g;
            dst[r0 + t]     = acc[mi][ni][0];
            dst[r1 + t]     = acc[mi][ni][1];
            dst[r0 + t + 8] = acc[mi][ni][2];
            dst[r1 + t + 8] = acc[mi][ni][3];
        }
    }
}

// ---------------------------------------------------------------------------
// Scan: inclusive complex scan over t, in place on g_bx (one warp per (b,h))
// ---------------------------------------------------------------------------
__global__ __launch_bounds__(256)
void scan_kernel() {
    int wg   = (blockIdx.x * blockDim.x + threadIdx.x) >> 5;
    int lane = threadIdx.x & 31;
    if (wg >= BATCH * HID) return;
    int b = wg >> 8;
    int h = wg & (HID - 1);

    float lre = g_lam_re[h], lim = g_lam_im[h];
    float pdre[5], pdim[5];
    {
        float pr = lre, pi = lim;
        pdre[0] = pr; pdim[0] = pi;
#pragma unroll
        for (int s = 1; s < 5; s++) {
            float nr = pr * pr - pi * pi;
            float ni = 2.f * pr * pi;
            pdre[s] = nr; pdim[s] = ni;
            pr = nr; pi = ni;
        }
    }
    float mag = g_mag[h], th = g_th[h];
    float mp  = powf(mag, (float)(lane + 1));
    float sa, ca;
    sincosf(th * (float)(lane + 1), &sa, &ca);
    float cpre = mp * ca, cpim = mp * sa;

    float carry_re = 0.f, carry_im = 0.f;
    size_t base = ((size_t)b * HID + h) * TLEN;

    float nxr = g_bx_re[base + lane];
    float nxi = g_bx_im[base + lane];

    for (int c = 0; c < TLEN / 32; c++) {
        float xr = nxr, xi = nxi;
        if (c + 1 < TLEN / 32) {
            nxr = g_bx_re[base + (c + 1) * 32 + lane];
            nxi = g_bx_im[base + (c + 1) * 32 + lane];
        }
#pragma unroll
        for (int s = 0; s < 5; s++) {
            int d = 1 << s;
            float yr = __shfl_up_sync(0xffffffffu, xr, d);
            float yi = __shfl_up_sync(0xffffffffu, xi, d);
            if (lane >= d) {
                xr += pdre[s] * yr - pdim[s] * yi;
                xi += pdre[s] * yi + pdim[s] * yr;
            }
        }
        xr += cpre * carry_re - cpim * carry_im;
        xi += cpre * carry_im + cpim * carry_re;

        g_bx_re[base + c * 32 + lane] = xr;
        g_bx_im[base + c * 32 + lane] = xi;

        carry_re = __shfl_sync(0xffffffffu, xr, 31);
        carry_im = __shfl_sync(0xffffffffu, xi, 31);
    }
}

// ---------------------------------------------------------------------------
// GEMM2 (tf32 tensor): Y[t][o] = sum_{k<640} A[k][t] * Wt2[k][o]
// A rows: k<256 -> bx_re[h=k], k<512 -> bx_im, else -> g_xt[i=k-512].
// Block: 128 t x 128 o, 8 warps (2m x 4n).
// ---------------------------------------------------------------------------
__global__ __launch_bounds__(256)
void gemm2_kernel(float* __restrict__ Y) {
    __shared__ float As[32 * PITCH];
    __shared__ float Ws[32 * PITCH];

    int tid = threadIdx.x, lane = tid & 31, wid = tid >> 5;
    int warp_m = wid >> 2, warp_n = wid & 3;
    int g = lane >> 2, tig = lane & 3;
    int b = blockIdx.y, t0 = blockIdx.x * 128;

    float acc[4][4][4];
#pragma unroll
    for (int mi = 0; mi < 4; mi++)
#pragma unroll
        for (int ni = 0; ni < 4; ni++)
#pragma unroll
            for (int q = 0; q < 4; q++) acc[mi][ni][q] = 0.f;

    const int row = tid >> 3;
    const int cb  = tid & 7;

    for (int kc = 0; kc < 640; kc += 32) {
        const float* arow;
        int k = kc + row;
        if (k < 256)      arow = g_bx_re + ((size_t)b * HID + k) * TLEN + t0;
        else if (k < 512) arow = g_bx_im + ((size_t)b * HID + (k - 256)) * TLEN + t0;
        else              arow = g_xt   + ((size_t)b * INDIM + (k - 512)) * TLEN + t0;
        const float* wrow = g_wt2 + (size_t)k * OUTDIM;
#pragma unroll
        for (int r = 0; r < 4; r++) {
            int c = cb + 8 * r;
            float4 v = *(const float4*)(arow + 4 * c);
            float4 w;
            w.x = to_tf32(v.x); w.y = to_tf32(v.y); w.z = to_tf32(v.z); w.w = to_tf32(v.w);
            *(float4*)&As[row * PITCH + 4 * c] = w;
            float4 u = *(const float4*)(wrow + 4 * c);
            float4 s;
            s.x = to_tf32(u.x); s.y = to_tf32(u.y); s.z = to_tf32(u.z); s.w = to_tf32(u.w);
            *(float4*)&Ws[row * PITCH + 4 * c] = s;
        }
        __syncthreads();

#pragma unroll
        for (int ks = 0; ks < 4; ks++) {
            int k0r = (ks * 8 + tig) * PITCH;
            int k1r = k0r + 4 * PITCH;
            float a[4][4], bb[4][2];
#pragma unroll
            for (int mi = 0; mi < 4; mi++) {
                int m = warp_m * 64 + mi * 16 + g;
                a[mi][0] = As[k0r + m];
                a[mi][1] = As[k0r + m + 8];
                a[mi][2] = As[k1r + m];
                a[mi][3] = As[k1r + m + 8];
            }
#pragma unroll
            for (int ni = 0; ni < 4; ni++) {
                int n = warp_n * 32 + ni * 8 + g;
                bb[ni][0] = Ws[k0r + n];
                bb[ni][1] = Ws[k1r + n];
            }
#pragma unroll
            for (int mi = 0; mi < 4; mi++)
#pragma unroll
                for (int ni = 0; ni < 4; ni++)
                    mma8(acc[mi][ni][0], acc[mi][ni][1], acc[mi][ni][2], acc[mi][ni][3],
                         a[mi][0], a[mi][1], a[mi][2], a[mi][3],
                         bb[ni][0], bb[ni][1]);
        }
        __syncthreads();
    }

    // epilogue: Y[b][t][o], float2 stores
#pragma unroll
    for (int mi = 0; mi < 4; mi++) {
        int t = t0 + warp_m * 64 + mi * 16 + g;
        size_t yb0 = ((size_t)b * TLEN + t) * OUTDIM;
        size_t yb1 = ((size_t)b * TLEN + t + 8) * OUTDIM;
#pragma unroll
        for (int ni = 0; ni < 4; ni++) {
            int o = warp_n * 32 + ni * 8 + 2 * tig;
            float2 v0 = make_float2(acc[mi][ni][0], acc[mi][ni][1]);
            float2 v1 = make_float2(acc[mi][ni][2], acc[mi][ni][3]);
            *(float2*)&Y[yb0 + o] = v0;
            *(float2*)&Y[yb1 + o] = v1;
        }
    }
}

// ---------------------------------------------------------------------------
extern "C" void kernel_launch(void* const* d_in, const int* in_sizes, int n_in,
                              void* d_out, int out_size) {
    const float* X         = (const float*)d_in[0];
    const float* nu_log    = (const float*)d_in[1];
    const float* theta_log = (const float*)d_in[2];
    const float* B_re      = (const float*)d_in[3];
    const float* B_im      = (const float*)d_in[4];
    const float* C_re      = (const float*)d_in[5];
    const float* C_im      = (const float*)d_in[6];
    const float* D         = (const float*)d_in[7];
    float* Y = (float*)d_out;

    params_kernel<<<1, 256>>>(nu_log, theta_log);

    int prep_total = 640 * OUTDIM + INDIM * 2 * HID;
    prep_w_kernel<<<(prep_total + 255) / 256, 256>>>(B_re, B_im, C_re, C_im, D);

    dim3 gxt(TLEN / 32, INDIM / 32, BATCH);
    prep_xt_kernel<<<gxt, 256>>>(X);

    dim3 g1(TLEN / 128, 4, BATCH);
    gemm1_kernel<<<g1, 256>>>();

    scan_kernel<<<(BATCH * HID * 32) / 256, 256>>>();

    dim3 g2(TLEN / 128, BATCH);
    gemm2_kernel<<<g2, 256>>>(Y);
}

// round 4
// speedup vs baseline: 3.5765x; 1.3819x over previous
#include <cuda_runtime.h>
#include <cstdint>

#define BATCH 8
#define TLEN 4096
#define INDIM 128
#define OUTDIM 128
#define HID 256
#define PITCH 136            // floats per smem row (16B-aligned: 544B)
#define KC 16                // K-chunk
#define BUFSZ (KC * PITCH)   // floats per buffer

// ---- scratch (device globals: allocation-free rule) ----
__device__ float g_lam_re[HID];
__device__ float g_lam_im[HID];
__device__ float g_gamma[HID];
__device__ float g_mag[HID];
__device__ float g_th[HID];
__device__ float g_bx_re[(size_t)BATCH * HID * TLEN];    // [b][h][t]
__device__ float g_bx_im[(size_t)BATCH * HID * TLEN];
__device__ float g_xt[(size_t)BATCH * INDIM * TLEN];     // [b][i][t] (tf32-rounded)
__device__ float g_wt2[640 * OUTDIM];                    // [k][o]: Cre^T | -Cim^T | D^T (tf32)
__device__ float g_wg1[INDIM * 2 * HID];                 // [i][n]  (tf32, gamma-scaled)

// ---- helpers ----
__device__ __forceinline__ float to_tf32(float x) {
    unsigned u;
    asm("cvt.rna.tf32.f32 %0, %1;" : "=r"(u) : "f"(x));
    return __uint_as_float(u);
}
__device__ __forceinline__ void mma8(float& d0, float& d1, float& d2, float& d3,
                                     float a0, float a1, float a2, float a3,
                                     float b0, float b1) {
    asm("mma.sync.aligned.m16n8k8.row.col.f32.tf32.tf32.f32 "
        "{%0,%1,%2,%3}, {%4,%5,%6,%7}, {%8,%9}, {%0,%1,%2,%3};"
        : "+f"(d0), "+f"(d1), "+f"(d2), "+f"(d3)
        : "r"(__float_as_uint(a0)), "r"(__float_as_uint(a1)),
          "r"(__float_as_uint(a2)), "r"(__float_as_uint(a3)),
          "r"(__float_as_uint(b0)), "r"(__float_as_uint(b1)));
}
__device__ __forceinline__ unsigned smem_u32(const void* p) {
    return (unsigned)__cvta_generic_to_shared(p);
}
__device__ __forceinline__ void cp16(unsigned s, const void* g) {
    asm volatile("cp.async.cg.shared.global [%0], [%1], 16;" :: "r"(s), "l"(g));
}
__device__ __forceinline__ void cp_commit() {
    asm volatile("cp.async.commit_group;");
}
__device__ __forceinline__ void cp_wait1() {
    asm volatile("cp.async.wait_group 1;");
}
__device__ __forceinline__ void cp_wait0() {
    asm volatile("cp.async.wait_group 0;");
}

// ---------------------------------------------------------------------------
// Kernel 0: per-channel recurrence parameters
// ---------------------------------------------------------------------------
__global__ void params_kernel(const float* __restrict__ nu_log,
                              const float* __restrict__ theta_log) {
    int h = threadIdx.x;
    if (h < HID) {
        float mag = expf(-expf(nu_log[h]));
        float th  = expf(theta_log[h]);
        g_mag[h] = mag;
        g_th[h]  = th;
        g_lam_re[h] = mag * cosf(th);
        g_lam_im[h] = mag * sinf(th);
        g_gamma[h]  = sqrtf(fmaxf(1.0f - mag * mag, 0.0f));
    }
}

// ---------------------------------------------------------------------------
// Prep: pack weight matrices (transposed, scaled/negated, tf32-rounded)
// ---------------------------------------------------------------------------
__global__ __launch_bounds__(256)
void prep_w_kernel(const float* __restrict__ Bre, const float* __restrict__ Bim,
                   const float* __restrict__ Cre, const float* __restrict__ Cim,
                   const float* __restrict__ Dm) {
    int idx = blockIdx.x * 256 + threadIdx.x;
    if (idx < 640 * OUTDIM) {
        int o = idx & 127;
        int k = idx >> 7;
        float v;
        if (k < 256)       v =  Cre[(size_t)o * HID + k];
        else if (k < 512)  v = -Cim[(size_t)o * HID + (k - 256)];
        else               v =  Dm[(size_t)o * INDIM + (k - 512)];
        g_wt2[k * OUTDIM + o] = to_tf32(v);
    } else {
        int j = idx - 640 * OUTDIM;
        if (j < INDIM * 2 * HID) {
            int n = j & 511;
            int i = j >> 9;
            int h = n & 255;
            float w = (n < 256) ? Bre[(size_t)h * INDIM + i] : Bim[(size_t)h * INDIM + i];
            g_wg1[i * 512 + n] = to_tf32(g_gamma[h] * w);
        }
    }
}

// ---------------------------------------------------------------------------
// Prep: transpose X -> g_xt[b][i][t] (tf32-rounded)
// ---------------------------------------------------------------------------
__global__ __launch_bounds__(256)
void prep_xt_kernel(const float* __restrict__ X) {
    __shared__ float tile[32][33];
    int b  = blockIdx.z;
    int t0 = blockIdx.x * 32;
    int i0 = blockIdx.y * 32;
    int tid = threadIdx.x;
#pragma unroll
    for (int r = 0; r < 4; r++) {
        int idx = tid + 256 * r;
        int tl = idx >> 5, il = idx & 31;
        tile[tl][il] = X[((size_t)b * TLEN + t0 + tl) * INDIM + i0 + il];
    }
    __syncthreads();
#pragma unroll
    for (int r = 0; r < 4; r++) {
        int idx = tid + 256 * r;
        int il = idx >> 5, tl = idx & 31;
        g_xt[((size_t)b * INDIM + i0 + il) * TLEN + t0 + tl] = to_tf32(tile[tl][il]);
    }
}

// ---------------------------------------------------------------------------
// GEMM1 (tf32 tensor, cp.async double-buffered):
//   out[n][t] = sum_i g_xt[i][t] * Wg1[i][n]
// Block 128t x 128n, 8 warps (2m x 4n). Writes raw fp32 bx (scan input).
// ---------------------------------------------------------------------------
__global__ __launch_bounds__(256)
void gemm1_kernel() {
    __shared__ float As[2 * BUFSZ];
    __shared__ float Ws[2 * BUFSZ];

    int tid = threadIdx.x, lane = tid & 31, wid = tid >> 5;
    int warp_m = wid >> 2, warp_n = wid & 3;
    int g = lane >> 2, tig = lane & 3;
    int b = blockIdx.z, t0 = blockIdx.x * 128, n0 = blockIdx.y * 128;

    float acc[4][4][4];
#pragma unroll
    for (int mi = 0; mi < 4; mi++)
#pragma unroll
        for (int ni = 0; ni < 4; ni++)
#pragma unroll
            for (int q = 0; q < 4; q++) acc[mi][ni][q] = 0.f;

    const int row = tid >> 4;      // 0..15
    const int cq  = tid & 15;      // chunk col
    const int NCH = INDIM / KC;    // 8

    // issue chunk 0
    {
        const float* arow = g_xt + ((size_t)b * INDIM + row) * TLEN + t0;
        const float* wrow = g_wg1 + (size_t)row * 512 + n0;
        unsigned sa = smem_u32(&As[row * PITCH]);
        unsigned sw = smem_u32(&Ws[row * PITCH]);
        cp16(sa + 16 * cq, arow + 4 * cq);
        cp16(sa + 16 * (cq + 16), arow + 4 * (cq + 16));
        cp16(sw + 16 * cq, wrow + 4 * cq);
        cp16(sw + 16 * (cq + 16), wrow + 4 * (cq + 16));
        cp_commit();
    }

    for (int c = 0; c < NCH; c++) {
        if (c + 1 < NCH) {
            int buf = (c + 1) & 1;
            int k = (c + 1) * KC + row;
            const float* arow = g_xt + ((size_t)b * INDIM + k) * TLEN + t0;
            const float* wrow = g_wg1 + (size_t)k * 512 + n0;
            unsigned sa = smem_u32(&As[buf * BUFSZ + row * PITCH]);
            unsigned sw = smem_u32(&Ws[buf * BUFSZ + row * PITCH]);
            cp16(sa + 16 * cq, arow + 4 * cq);
            cp16(sa + 16 * (cq + 16), arow + 4 * (cq + 16));
            cp16(sw + 16 * cq, wrow + 4 * cq);
            cp16(sw + 16 * (cq + 16), wrow + 4 * (cq + 16));
            cp_commit();
            cp_wait1();
        } else {
            cp_wait0();
        }
        __syncthreads();

        int bb0 = (c & 1) * BUFSZ;
#pragma unroll
        for (int ks = 0; ks < 2; ks++) {
            int k0r = bb0 + (ks * 8 + tig) * PITCH;
            int k1r = k0r + 4 * PITCH;
            float a[4][4], bb[4][2];
#pragma unroll
            for (int mi = 0; mi < 4; mi++) {
                int m = warp_m * 64 + mi * 16 + g;
                a[mi][0] = As[k0r + m];
                a[mi][1] = As[k0r + m + 8];
                a[mi][2] = As[k1r + m];
                a[mi][3] = As[k1r + m + 8];
            }
#pragma unroll
            for (int ni = 0; ni < 4; ni++) {
                int n = warp_n * 32 + ni * 8 + g;
                bb[ni][0] = Ws[k0r + n];
                bb[ni][1] = Ws[k1r + n];
            }
#pragma unroll
            for (int mi = 0; mi < 4; mi++)
#pragma unroll
                for (int ni = 0; ni < 4; ni++)
                    mma8(acc[mi][ni][0], acc[mi][ni][1], acc[mi][ni][2], acc[mi][ni][3],
                         a[mi][0], a[mi][1], a[mi][2], a[mi][3],
                         bb[ni][0], bb[ni][1]);
        }
        __syncthreads();
    }

    // epilogue: scatter to [b][h][t] (raw fp32)
#pragma unroll
    for (int ni = 0; ni < 4; ni++) {
        int n = n0 + warp_n * 32 + ni * 8 + 2 * tig;
        float* dst = (n < 256) ? g_bx_re : g_bx_im;
        int h = n & 255;
        size_t r0 = ((size_t)b * HID + h) * TLEN;
        size_t r1 = ((size_t)b * HID + h + 1) * TLEN;
#pragma unroll
        for (int mi = 0; mi < 4; mi++) {
            int t = t0 + warp_m * 64 + mi * 16 + g;
            dst[r0 + t]     = acc[mi][ni][0];
            dst[r1 + t]     = acc[mi][ni][1];
            dst[r0 + t + 8] = acc[mi][ni][2];
            dst[r1 + t + 8] = acc[mi][ni][3];
        }
    }
}

// ---------------------------------------------------------------------------
// Scan: inclusive complex scan over t, 4 elems/lane (128 t per warp iter),
// in place on g_bx; stores tf32-rounded (gemm2 consumes raw).
// ---------------------------------------------------------------------------
__global__ __launch_bounds__(256)
void scan_kernel() {
    int wg   = (blockIdx.x * blockDim.x + threadIdx.x) >> 5;
    int lane = threadIdx.x & 31;
    if (wg >= BATCH * HID) return;
    int b = wg >> 8;
    int h = wg & (HID - 1);

    float l1r = g_lam_re[h], l1i = g_lam_im[h];
    float l2r = l1r * l1r - l1i * l1i, l2i = 2.f * l1r * l1i;
    float l3r = l2r * l1r - l2i * l1i, l3i = l2r * l1i + l2i * l1r;
    float l4r = l2r * l2r - l2i * l2i, l4i = 2.f * l2r * l2i;

    // KS powers: (lam^4)^(2^s)
    float pdr[5], pdi[5];
    pdr[0] = l4r; pdi[0] = l4i;
#pragma unroll
    for (int s = 1; s < 5; s++) {
        pdr[s] = pdr[s-1] * pdr[s-1] - pdi[s-1] * pdi[s-1];
        pdi[s] = 2.f * pdr[s-1] * pdi[s-1];
    }
    // lam^(4*lane) for chunk-carry folding
    float mag = g_mag[h], th = g_th[h];
    float mp  = powf(mag, 4.f * (float)lane);
    float sa, ca;
    sincosf(th * 4.f * (float)lane, &sa, &ca);
    float c4r = mp * ca, c4i = mp * sa;

    float ccr = 0.f, cci = 0.f;
    size_t base = ((size_t)b * HID + h) * TLEN;

    for (int c = 0; c < TLEN / 128; c++) {
        size_t off = base + (size_t)c * 128 + lane * 4;
        float4 xr = *(const float4*)&g_bx_re[off];
        float4 xi = *(const float4*)&g_bx_im[off];

        // within-lane serial scan
        float y0r = xr.x,                         y0i = xi.x;
        float y1r = xr.y + l1r * y0r - l1i * y0i, y1i = xi.y + l1r * y0i + l1i * y0r;
        float y2r = xr.z + l1r * y1r - l1i * y1i, y2i = xi.z + l1r * y1i + l1i * y1r;
        float y3r = xr.w + l1r * y2r - l1i * y2i, y3i = xi.w + l1r * y2i + l1i * y2r;

        // Kogge-Stone across lanes on segment totals (decay lam^4)
        float sr = y3r, si = y3i;
#pragma unroll
        for (int s = 0; s < 5; s++) {
            int d = 1 << s;
            float tr = __shfl_up_sync(0xffffffffu, sr, d);
            float ti = __shfl_up_sync(0xffffffffu, si, d);
            if (lane >= d) {
                sr += pdr[s] * tr - pdi[s] * ti;
                si += pdr[s] * ti + pdi[s] * tr;
            }
        }
        // carry-in = previous lane's inclusive total, plus chunk carry
        float qr = __shfl_up_sync(0xffffffffu, sr, 1);
        float qi = __shfl_up_sync(0xffffffffu, si, 1);
        if (lane == 0) { qr = 0.f; qi = 0.f; }
        qr += c4r * ccr - c4i * cci;
        qi += c4r * cci + c4i * ccr;

        float o0r = y0r + l1r * qr - l1i * qi, o0i = y0i + l1r * qi + l1i * qr;
        float o1r = y1r + l2r * qr - l2i * qi, o1i = y1i + l2r * qi + l2i * qr;
        float o2r = y2r + l3r * qr - l3i * qi, o2i = y2i + l3r * qi + l3i * qr;
        float o3r = y3r + l4r * qr - l4i * qi, o3i = y3i + l4r * qi + l4i * qr;

        ccr = __shfl_sync(0xffffffffu, o3r, 31);
        cci = __shfl_sync(0xffffffffu, o3i, 31);

        float4 wr = make_float4(to_tf32(o0r), to_tf32(o1r), to_tf32(o2r), to_tf32(o3r));
        float4 wi = make_float4(to_tf32(o0i), to_tf32(o1i), to_tf32(o2i), to_tf32(o3i));
        *(float4*)&g_bx_re[off] = wr;
        *(float4*)&g_bx_im[off] = wi;
    }
}

// ---------------------------------------------------------------------------
// GEMM2 (tf32 tensor, cp.async double-buffered):
//   Y[t][o] = sum_{k<640} A[k][t] * Wt2[k][o]
// A rows: k<256 -> bx_re, k<512 -> bx_im, else g_xt. Block 128t x 128o.
// ---------------------------------------------------------------------------
__global__ __launch_bounds__(256)
void gemm2_kernel(float* __restrict__ Y) {
    __shared__ float As[2 * BUFSZ];
    __shared__ float Ws[2 * BUFSZ];

    int tid = threadIdx.x, lane = tid & 31, wid = tid >> 5;
    int warp_m = wid >> 2, warp_n = wid & 3;
    int g = lane >> 2, tig = lane & 3;
    int b = blockIdx.y, t0 = blockIdx.x * 128;

    float acc[4][4][4];
#pragma unroll
    for (int mi = 0; mi < 4; mi++)
#pragma unroll
        for (int ni = 0; ni < 4; ni++)
#pragma unroll
            for (int q = 0; q < 4; q++) acc[mi][ni][q] = 0.f;

    const int row = tid >> 4;
    const int cq  = tid & 15;
    const int NCH = 640 / KC;      // 40

    // A-row source select
    auto arow_of = [&](int k) -> const float* {
        if (k < 256)      return g_bx_re + ((size_t)b * HID + k) * TLEN + t0;
        else if (k < 512) return g_bx_im + ((size_t)b * HID + (k - 256)) * TLEN + t0;
        else              return g_xt   + ((size_t)b * INDIM + (k - 512)) * TLEN + t0;
    };

    // issue chunk 0
    {
        const float* arow = arow_of(row);
        const float* wrow = g_wt2 + (size_t)row * OUTDIM;
        unsigned sa = smem_u32(&As[row * PITCH]);
        unsigned sw = smem_u32(&Ws[row * PITCH]);
        cp16(sa + 16 * cq, arow + 4 * cq);
        cp16(sa + 16 * (cq + 16), arow + 4 * (cq + 16));
        cp16(sw + 16 * cq, wrow + 4 * cq);
        cp16(sw + 16 * (cq + 16), wrow + 4 * (cq + 16));
        cp_commit();
    }

    for (int c = 0; c < NCH; c++) {
        if (c + 1 < NCH) {
            int buf = (c + 1) & 1;
            int k = (c + 1) * KC + row;
            const float* arow = arow_of(k);
            const float* wrow = g_wt2 + (size_t)k * OUTDIM;
            unsigned sa = smem_u32(&As[buf * BUFSZ + row * PITCH]);
            unsigned sw = smem_u32(&Ws[buf * BUFSZ + row * PITCH]);
            cp16(sa + 16 * cq, arow + 4 * cq);
            cp16(sa + 16 * (cq + 16), arow + 4 * (cq + 16));
            cp16(sw + 16 * cq, wrow + 4 * cq);
            cp16(sw + 16 * (cq + 16), wrow + 4 * (cq + 16));
            cp_commit();
            cp_wait1();
        } else {
            cp_wait0();
        }
        __syncthreads();

        int bb0 = (c & 1) * BUFSZ;
#pragma unroll
        for (int ks = 0; ks < 2; ks++) {
            int k0r = bb0 + (ks * 8 + tig) * PITCH;
            int k1r = k0r + 4 * PITCH;
            float a[4][4], bb[4][2];
#pragma unroll
            for (int mi = 0; mi < 4; mi++) {
                int m = warp_m * 64 + mi * 16 + g;
                a[mi][0] = As[k0r + m];
                a[mi][1] = As[k0r + m + 8];
                a[mi][2] = As[k1r + m];
                a[mi][3] = As[k1r + m + 8];
            }
#pragma unroll
            for (int ni = 0; ni < 4; ni++) {
                int n = warp_n * 32 + ni * 8 + g;
                bb[ni][0] = Ws[k0r + n];
                bb[ni][1] = Ws[k1r + n];
            }
#pragma unroll
            for (int mi = 0; mi < 4; mi++)
#pragma unroll
                for (int ni = 0; ni < 4; ni++)
                    mma8(acc[mi][ni][0], acc[mi][ni][1], acc[mi][ni][2], acc[mi][ni][3],
                         a[mi][0], a[mi][1], a[mi][2], a[mi][3],
                         bb[ni][0], bb[ni][1]);
        }
        __syncthreads();
    }

    // epilogue: Y[b][t][o], float2 stores
#pragma unroll
    for (int mi = 0; mi < 4; mi++) {
        int t = t0 + warp_m * 64 + mi * 16 + g;
        size_t yb0 = ((size_t)b * TLEN + t) * OUTDIM;
        size_t yb1 = ((size_t)b * TLEN + t + 8) * OUTDIM;
#pragma unroll
        for (int ni = 0; ni < 4; ni++) {
            int o = warp_n * 32 + ni * 8 + 2 * tig;
            *(float2*)&Y[yb0 + o] = make_float2(acc[mi][ni][0], acc[mi][ni][1]);
            *(float2*)&Y[yb1 + o] = make_float2(acc[mi][ni][2], acc[mi][ni][3]);
        }
    }
}

// ---------------------------------------------------------------------------
extern "C" void kernel_launch(void* const* d_in, const int* in_sizes, int n_in,
                              void* d_out, int out_size) {
    const float* X         = (const float*)d_in[0];
    const float* nu_log    = (const float*)d_in[1];
    const float* theta_log = (const float*)d_in[2];
    const float* B_re      = (const float*)d_in[3];
    const float* B_im      = (const float*)d_in[4];
    const float* C_re      = (const float*)d_in[5];
    const float* C_im      = (const float*)d_in[6];
    const float* D         = (const float*)d_in[7];
    float* Y = (float*)d_out;

    params_kernel<<<1, 256>>>(nu_log, theta_log);

    int prep_total = 640 * OUTDIM + INDIM * 2 * HID;
    prep_w_kernel<<<(prep_total + 255) / 256, 256>>>(B_re, B_im, C_re, C_im, D);

    dim3 gxt(TLEN / 32, INDIM / 32, BATCH);
    prep_xt_kernel<<<gxt, 256>>>(X);

    dim3 g1(TLEN / 128, 4, BATCH);
    gemm1_kernel<<<g1, 256>>>();

    scan_kernel<<<(BATCH * HID * 32) / 256, 256>>>();

    dim3 g2(TLEN / 128, BATCH);
    gemm2_kernel<<<g2, 256>>>(Y);
}

// round 5
// speedup vs baseline: 3.9786x; 1.1124x over previous
#include <cuda_runtime.h>
#include <cstdint>

#define BATCH 8
#define TLEN 4096
#define INDIM 128
#define OUTDIM 128
#define HID 256
#define PITCH 136            // floats per smem row (544B, 16B-aligned)
#define KC 32                // K-chunk
#define BUFSZ (KC * PITCH)   // floats per buffer (4352)
#define SMEM_GEMM (4 * BUFSZ * 4)  // bytes: 2 arrays x 2 buffers

// ---- scratch (device globals: allocation-free rule) ----
__device__ float g_lam_re[HID];
__device__ float g_lam_im[HID];
__device__ float g_gamma[HID];
__device__ float g_mag[HID];
__device__ float g_th[HID];
__device__ float g_bx_re[(size_t)BATCH * HID * TLEN];    // [b][h][t]
__device__ float g_bx_im[(size_t)BATCH * HID * TLEN];
__device__ float g_xt[(size_t)BATCH * INDIM * TLEN];     // [b][i][t] (tf32-rounded)
__device__ float g_wt2[640 * OUTDIM];                    // [k][o]: Cre^T | -Cim^T | D^T (tf32)
__device__ float g_wg1[INDIM * 2 * HID];                 // [i][n]  (tf32, gamma-scaled)

// ---- helpers ----
__device__ __forceinline__ float to_tf32(float x) {
    unsigned u;
    asm("cvt.rna.tf32.f32 %0, %1;" : "=r"(u) : "f"(x));
    return __uint_as_float(u);
}
__device__ __forceinline__ void mma8(float& d0, float& d1, float& d2, float& d3,
                                     float a0, float a1, float a2, float a3,
                                     float b0, float b1) {
    asm("mma.sync.aligned.m16n8k8.row.col.f32.tf32.tf32.f32 "
        "{%0,%1,%2,%3}, {%4,%5,%6,%7}, {%8,%9}, {%0,%1,%2,%3};"
        : "+f"(d0), "+f"(d1), "+f"(d2), "+f"(d3)
        : "r"(__float_as_uint(a0)), "r"(__float_as_uint(a1)),
          "r"(__float_as_uint(a2)), "r"(__float_as_uint(a3)),
          "r"(__float_as_uint(b0)), "r"(__float_as_uint(b1)));
}
__device__ __forceinline__ unsigned smem_u32(const void* p) {
    return (unsigned)__cvta_generic_to_shared(p);
}
__device__ __forceinline__ void cp16(unsigned s, const void* g) {
    asm volatile("cp.async.cg.shared.global [%0], [%1], 16;" :: "r"(s), "l"(g));
}
__device__ __forceinline__ void cp_commit() { asm volatile("cp.async.commit_group;"); }
__device__ __forceinline__ void cp_wait1()  { asm volatile("cp.async.wait_group 1;"); }
__device__ __forceinline__ void cp_wait0()  { asm volatile("cp.async.wait_group 0;"); }

// ---------------------------------------------------------------------------
// Kernel 0: per-channel recurrence parameters
// ---------------------------------------------------------------------------
__global__ void params_kernel(const float* __restrict__ nu_log,
                              const float* __restrict__ theta_log) {
    int h = threadIdx.x;
    if (h < HID) {
        float mag = expf(-expf(nu_log[h]));
        float th  = expf(theta_log[h]);
        g_mag[h] = mag;
        g_th[h]  = th;
        g_lam_re[h] = mag * cosf(th);
        g_lam_im[h] = mag * sinf(th);
        g_gamma[h]  = sqrtf(fmaxf(1.0f - mag * mag, 0.0f));
    }
}

// ---------------------------------------------------------------------------
// Prep: pack weight matrices (transposed, scaled/negated, tf32-rounded)
// ---------------------------------------------------------------------------
__global__ __launch_bounds__(256)
void prep_w_kernel(const float* __restrict__ Bre, const float* __restrict__ Bim,
                   const float* __restrict__ Cre, const float* __restrict__ Cim,
                   const float* __restrict__ Dm) {
    int idx = blockIdx.x * 256 + threadIdx.x;
    if (idx < 640 * OUTDIM) {
        int o = idx & 127;
        int k = idx >> 7;
        float v;
        if (k < 256)       v =  Cre[(size_t)o * HID + k];
        else if (k < 512)  v = -Cim[(size_t)o * HID + (k - 256)];
        else               v =  Dm[(size_t)o * INDIM + (k - 512)];
        g_wt2[k * OUTDIM + o] = to_tf32(v);
    } else {
        int j = idx - 640 * OUTDIM;
        if (j < INDIM * 2 * HID) {
            int n = j & 511;
            int i = j >> 9;
            int h = n & 255;
            float w = (n < 256) ? Bre[(size_t)h * INDIM + i] : Bim[(size_t)h * INDIM + i];
            g_wg1[i * 512 + n] = to_tf32(g_gamma[h] * w);
        }
    }
}

// ---------------------------------------------------------------------------
// Prep: transpose X -> g_xt[b][i][t] (tf32-rounded)
// ---------------------------------------------------------------------------
__global__ __launch_bounds__(256)
void prep_xt_kernel(const float* __restrict__ X) {
    __shared__ float tile[32][33];
    int b  = blockIdx.z;
    int t0 = blockIdx.x * 32;
    int i0 = blockIdx.y * 32;
    int tid = threadIdx.x;
#pragma unroll
    for (int r = 0; r < 4; r++) {
        int idx = tid + 256 * r;
        int tl = idx >> 5, il = idx & 31;
        tile[tl][il] = X[((size_t)b * TLEN + t0 + tl) * INDIM + i0 + il];
    }
    __syncthreads();
#pragma unroll
    for (int r = 0; r < 4; r++) {
        int idx = tid + 256 * r;
        int il = idx >> 5, tl = idx & 31;
        g_xt[((size_t)b * INDIM + i0 + il) * TLEN + t0 + tl] = to_tf32(tile[tl][il]);
    }
}

// ---------------------------------------------------------------------------
// GEMM fill helper: one KC=32 x 128 chunk of A and W via cp.async
// row = tid>>3 (0..31), cq = tid&7, 4x float4 per array per thread
// ---------------------------------------------------------------------------
__device__ __forceinline__ void fill_chunk(float* As, float* Ws, int buf,
                                           const float* arow, const float* wrow,
                                           int row, int cq) {
    unsigned sa = smem_u32(&As[buf * BUFSZ + row * PITCH]);
    unsigned sw = smem_u32(&Ws[buf * BUFSZ + row * PITCH]);
#pragma unroll
    for (int r = 0; r < 4; r++) {
        int c = cq + 8 * r;
        cp16(sa + 16 * c, arow + 4 * c);
        cp16(sw + 16 * c, wrow + 4 * c);
    }
}

// ---------------------------------------------------------------------------
// MMA compute for one KC=32 chunk (4 k8-steps)
// ---------------------------------------------------------------------------
__device__ __forceinline__ void compute_chunk(const float* As, const float* Ws,
                                              int bb0, int warp_m, int warp_n,
                                              int g, int tig, float acc[4][4][4]) {
#pragma unroll
    for (int ks = 0; ks < 4; ks++) {
        int k0r = bb0 + (ks * 8 + tig) * PITCH;
        int k1r = k0r + 4 * PITCH;
        float a[4][4], bb[4][2];
#pragma unroll
        for (int mi = 0; mi < 4; mi++) {
            int m = warp_m * 64 + mi * 16 + g;
            a[mi][0] = As[k0r + m];
            a[mi][1] = As[k0r + m + 8];
            a[mi][2] = As[k1r + m];
            a[mi][3] = As[k1r + m + 8];
        }
#pragma unroll
        for (int ni = 0; ni < 4; ni++) {
            int n = warp_n * 32 + ni * 8 + g;
            bb[ni][0] = Ws[k0r + n];
            bb[ni][1] = Ws[k1r + n];
        }
#pragma unroll
        for (int mi = 0; mi < 4; mi++)
#pragma unroll
            for (int ni = 0; ni < 4; ni++)
                mma8(acc[mi][ni][0], acc[mi][ni][1], acc[mi][ni][2], acc[mi][ni][3],
                     a[mi][0], a[mi][1], a[mi][2], a[mi][3],
                     bb[ni][0], bb[ni][1]);
    }
}

// ---------------------------------------------------------------------------
// GEMM1 (tf32 tensor, cp.async double-buffered, KC=32):
//   out[n][t] = sum_i g_xt[i][t] * Wg1[i][n]
// ---------------------------------------------------------------------------
__global__ __launch_bounds__(256)
void gemm1_kernel() {
    extern __shared__ float smem[];
    float* As = smem;
    float* Ws = smem + 2 * BUFSZ;

    int tid = threadIdx.x, lane = tid & 31, wid = tid >> 5;
    int warp_m = wid >> 2, warp_n = wid & 3;
    int g = lane >> 2, tig = lane & 3;
    int b = blockIdx.z, t0 = blockIdx.x * 128, n0 = blockIdx.y * 128;

    float acc[4][4][4];
#pragma unroll
    for (int mi = 0; mi < 4; mi++)
#pragma unroll
        for (int ni = 0; ni < 4; ni++)
#pragma unroll
            for (int q = 0; q < 4; q++) acc[mi][ni][q] = 0.f;

    const int row = tid >> 3;      // 0..31
    const int cq  = tid & 7;
    const int NCH = INDIM / KC;    // 4

    {
        const float* arow = g_xt + ((size_t)b * INDIM + row) * TLEN + t0;
        const float* wrow = g_wg1 + (size_t)row * 512 + n0;
        fill_chunk(As, Ws, 0, arow, wrow, row, cq);
        cp_commit();
    }

    for (int c = 0; c < NCH; c++) {
        if (c + 1 < NCH) {
            int k = (c + 1) * KC + row;
            const float* arow = g_xt + ((size_t)b * INDIM + k) * TLEN + t0;
            const float* wrow = g_wg1 + (size_t)k * 512 + n0;
            fill_chunk(As, Ws, (c + 1) & 1, arow, wrow, row, cq);
            cp_commit();
            cp_wait1();
        } else {
            cp_wait0();
        }
        __syncthreads();
        compute_chunk(As, Ws, (c & 1) * BUFSZ, warp_m, warp_n, g, tig, acc);
        __syncthreads();
    }

    // epilogue: scatter to [b][h][t] (raw fp32)
#pragma unroll
    for (int ni = 0; ni < 4; ni++) {
        int n = n0 + warp_n * 32 + ni * 8 + 2 * tig;
        float* dst = (n < 256) ? g_bx_re : g_bx_im;
        int h = n & 255;
        size_t r0 = ((size_t)b * HID + h) * TLEN;
        size_t r1 = ((size_t)b * HID + h + 1) * TLEN;
#pragma unroll
        for (int mi = 0; mi < 4; mi++) {
            int t = t0 + warp_m * 64 + mi * 16 + g;
            dst[r0 + t]     = acc[mi][ni][0];
            dst[r1 + t]     = acc[mi][ni][1];
            dst[r0 + t + 8] = acc[mi][ni][2];
            dst[r1 + t + 8] = acc[mi][ni][3];
        }
    }
}

// ---------------------------------------------------------------------------
// Scan: inclusive complex scan over t, 8 elems/lane (256 t per warp iter),
// prefetched; in place on g_bx; stores tf32-rounded.
// ---------------------------------------------------------------------------
__global__ __launch_bounds__(256)
void scan_kernel() {
    int wg   = (blockIdx.x * blockDim.x + threadIdx.x) >> 5;
    int lane = threadIdx.x & 31;
    if (wg >= BATCH * HID) return;
    int b = wg >> 8;
    int h = wg & (HID - 1);

    // lam^1..8
    float lr[8], li[8];
    lr[0] = g_lam_re[h]; li[0] = g_lam_im[h];
#pragma unroll
    for (int k = 1; k < 8; k++) {
        lr[k] = lr[k-1] * lr[0] - li[k-1] * li[0];
        li[k] = lr[k-1] * li[0] + li[k-1] * lr[0];
    }
    // KS powers (lam^8)^(2^s)
    float pdr[5], pdi[5];
    pdr[0] = lr[7]; pdi[0] = li[7];
#pragma unroll
    for (int s = 1; s < 5; s++) {
        pdr[s] = pdr[s-1] * pdr[s-1] - pdi[s-1] * pdi[s-1];
        pdi[s] = 2.f * pdr[s-1] * pdi[s-1];
    }
    // lam^(8*lane) for carry folding
    float mag = g_mag[h], th = g_th[h];
    float mp  = powf(mag, 8.f * (float)lane);
    float sa, ca;
    sincosf(th * 8.f * (float)lane, &sa, &ca);
    float c8r = mp * ca, c8i = mp * sa;

    float ccr = 0.f, cci = 0.f;
    size_t base = ((size_t)b * HID + h) * TLEN;
    const int NCH = TLEN / 256;    // 16

    // prefetch chunk 0
    size_t off = base + (size_t)lane * 8;
    float4 nr0 = *(const float4*)&g_bx_re[off];
    float4 nr1 = *(const float4*)&g_bx_re[off + 4];
    float4 ni0 = *(const float4*)&g_bx_im[off];
    float4 ni1 = *(const float4*)&g_bx_im[off + 4];

    for (int c = 0; c < NCH; c++) {
        float xr[8] = {nr0.x, nr0.y, nr0.z, nr0.w, nr1.x, nr1.y, nr1.z, nr1.w};
        float xi[8] = {ni0.x, ni0.y, ni0.z, ni0.w, ni1.x, ni1.y, ni1.z, ni1.w};
        size_t coff = off;
        if (c + 1 < NCH) {
            off += 256;
            nr0 = *(const float4*)&g_bx_re[off];
            nr1 = *(const float4*)&g_bx_re[off + 4];
            ni0 = *(const float4*)&g_bx_im[off];
            ni1 = *(const float4*)&g_bx_im[off + 4];
        }

        // within-lane serial scan
        float yr[8], yi[8];
        yr[0] = xr[0]; yi[0] = xi[0];
#pragma unroll
        for (int k = 1; k < 8; k++) {
            yr[k] = xr[k] + lr[0] * yr[k-1] - li[0] * yi[k-1];
            yi[k] = xi[k] + lr[0] * yi[k-1] + li[0] * yr[k-1];
        }

        // Kogge-Stone across lanes on segment totals (decay lam^8)
        float sr = yr[7], si = yi[7];
#pragma unroll
        for (int s = 0; s < 5; s++) {
            int d = 1 << s;
            float tr = __shfl_up_sync(0xffffffffu, sr, d);
            float ti = __shfl_up_sync(0xffffffffu, si, d);
            if (lane >= d) {
                sr += pdr[s] * tr - pdi[s] * ti;
                si += pdr[s] * ti + pdi[s] * tr;
            }
        }
        // carry-in for this lane's segment
        float qr = __shfl_up_sync(0xffffffffu, sr, 1);
        float qi = __shfl_up_sync(0xffffffffu, si, 1);
        if (lane == 0) { qr = 0.f; qi = 0.f; }
        qr += c8r * ccr - c8i * cci;
        qi += c8r * cci + c8i * ccr;

        float or_[8], oi_[8];
#pragma unroll
        for (int k = 0; k < 8; k++) {
            or_[k] = yr[k] + lr[k] * qr - li[k] * qi;
            oi_[k] = yi[k] + lr[k] * qi + li[k] * qr;
        }

        ccr = __shfl_sync(0xffffffffu, or_[7], 31);
        cci = __shfl_sync(0xffffffffu, oi_[7], 31);

        float4 w0 = make_float4(to_tf32(or_[0]), to_tf32(or_[1]), to_tf32(or_[2]), to_tf32(or_[3]));
        float4 w1 = make_float4(to_tf32(or_[4]), to_tf32(or_[5]), to_tf32(or_[6]), to_tf32(or_[7]));
        float4 v0 = make_float4(to_tf32(oi_[0]), to_tf32(oi_[1]), to_tf32(oi_[2]), to_tf32(oi_[3]));
        float4 v1 = make_float4(to_tf32(oi_[4]), to_tf32(oi_[5]), to_tf32(oi_[6]), to_tf32(oi_[7]));
        *(float4*)&g_bx_re[coff]     = w0;
        *(float4*)&g_bx_re[coff + 4] = w1;
        *(float4*)&g_bx_im[coff]     = v0;
        *(float4*)&g_bx_im[coff + 4] = v1;
    }
}

// ---------------------------------------------------------------------------
// GEMM2 (tf32 tensor, cp.async double-buffered, KC=32):
//   Y[t][o] = sum_{k<640} A[k][t] * Wt2[k][o]
// ---------------------------------------------------------------------------
__global__ __launch_bounds__(256)
void gemm2_kernel(float* __restrict__ Y) {
    extern __shared__ float smem[];
    float* As = smem;
    float* Ws = smem + 2 * BUFSZ;

    int tid = threadIdx.x, lane = tid & 31, wid = tid >> 5;
    int warp_m = wid >> 2, warp_n = wid & 3;
    int g = lane >> 2, tig = lane & 3;
    int b = blockIdx.y, t0 = blockIdx.x * 128;

    float acc[4][4][4];
#pragma unroll
    for (int mi = 0; mi < 4; mi++)
#pragma unroll
        for (int ni = 0; ni < 4; ni++)
#pragma unroll
            for (int q = 0; q < 4; q++) acc[mi][ni][q] = 0.f;

    const int row = tid >> 3;
    const int cq  = tid & 7;
    const int NCH = 640 / KC;      // 20

    auto arow_of = [&](int k) -> const float* {
        if (k < 256)      return g_bx_re + ((size_t)b * HID + k) * TLEN + t0;
        else if (k < 512) return g_bx_im + ((size_t)b * HID + (k - 256)) * TLEN + t0;
        else              return g_xt   + ((size_t)b * INDIM + (k - 512)) * TLEN + t0;
    };

    {
        fill_chunk(As, Ws, 0, arow_of(row), g_wt2 + (size_t)row * OUTDIM, row, cq);
        cp_commit();
    }

    for (int c = 0; c < NCH; c++) {
        if (c + 1 < NCH) {
            int k = (c + 1) * KC + row;
            fill_chunk(As, Ws, (c + 1) & 1, arow_of(k), g_wt2 + (size_t)k * OUTDIM, row, cq);
            cp_commit();
            cp_wait1();
        } else {
            cp_wait0();
        }
        __syncthreads();
        compute_chunk(As, Ws, (c & 1) * BUFSZ, warp_m, warp_n, g, tig, acc);
        __syncthreads();
    }

    // epilogue: Y[b][t][o], float2 stores
#pragma unroll
    for (int mi = 0; mi < 4; mi++) {
        int t = t0 + warp_m * 64 + mi * 16 + g;
        size_t yb0 = ((size_t)b * TLEN + t) * OUTDIM;
        size_t yb1 = ((size_t)b * TLEN + t + 8) * OUTDIM;
#pragma unroll
        for (int ni = 0; ni < 4; ni++) {
            int o = warp_n * 32 + ni * 8 + 2 * tig;
            *(float2*)&Y[yb0 + o] = make_float2(acc[mi][ni][0], acc[mi][ni][1]);
            *(float2*)&Y[yb1 + o] = make_float2(acc[mi][ni][2], acc[mi][ni][3]);
        }
    }
}

// ---------------------------------------------------------------------------
extern "C" void kernel_launch(void* const* d_in, const int* in_sizes, int n_in,
                              void* d_out, int out_size) {
    const float* X         = (const float*)d_in[0];
    const float* nu_log    = (const float*)d_in[1];
    const float* theta_log = (const float*)d_in[2];
    const float* B_re      = (const float*)d_in[3];
    const float* B_im      = (const float*)d_in[4];
    const float* C_re      = (const float*)d_in[5];
    const float* C_im      = (const float*)d_in[6];
    const float* D         = (const float*)d_in[7];
    float* Y = (float*)d_out;

    cudaFuncSetAttribute(gemm1_kernel, cudaFuncAttributeMaxDynamicSharedMemorySize, SMEM_GEMM);
    cudaFuncSetAttribute(gemm2_kernel, cudaFuncAttributeMaxDynamicSharedMemorySize, SMEM_GEMM);

    params_kernel<<<1, 256>>>(nu_log, theta_log);

    int prep_total = 640 * OUTDIM + INDIM * 2 * HID;
    prep_w_kernel<<<(prep_total + 255) / 256, 256>>>(B_re, B_im, C_re, C_im, D);

    dim3 gxt(TLEN / 32, INDIM / 32, BATCH);
    prep_xt_kernel<<<gxt, 256>>>(X);

    dim3 g1(TLEN / 128, 4, BATCH);
    gemm1_kernel<<<g1, 256, SMEM_GEMM>>>();

    scan_kernel<<<(BATCH * HID * 32) / 256, 256>>>();

    dim3 g2(TLEN / 128, BATCH);
    gemm2_kernel<<<g2, 256, SMEM_GEMM>>>(Y);
}

// round 6
// speedup vs baseline: 4.3120x; 1.0838x over previous
#include <cuda_runtime.h>
#include <cstdint>

#define BATCH 8
#define TLEN 4096
#define INDIM 128
#define OUTDIM 128
#define HID 256
#define PITCH 136              // floats per t-data smem row
#define KC 32                  // K-chunk
#define BBUF (KC * PITCH)      // t-data floats per buffer (4352)
#define WBUF 4096              // weight-fragment floats per buffer (4 k8 x 8 mt x 32 x 4)
#define SMEM_BYTES ((2 * BBUF + 2 * WBUF) * 4)   // 67584

// ---- scratch (device globals: allocation-free rule) ----
__device__ float g_lam_re[HID];
__device__ float g_lam_im[HID];
__device__ float g_gamma[HID];
__device__ float g_mag[HID];
__device__ float g_th[HID];
__device__ float g_bx_re[(size_t)BATCH * HID * TLEN];    // [b][h][t]
__device__ float g_bx_im[(size_t)BATCH * HID * TLEN];
__device__ float g_xt[(size_t)BATCH * INDIM * TLEN];     // [b][i][t] (tf32-rounded)
// weight fragments, mma m16n8k8 order: [K8][mt][lane][4]
__device__ float g_wf1[16 * 32 * 32 * 4];                // gemm1: M=512 (gamma*Bre | gamma*Bim), K=128
__device__ float g_wf2[80 * 8 * 32 * 4];                 // gemm2: M=128 (o), K=640 (Cre|-Cim|D)

// ---- helpers ----
__device__ __forceinline__ float to_tf32(float x) {
    unsigned u;
    asm("cvt.rna.tf32.f32 %0, %1;" : "=r"(u) : "f"(x));
    return __uint_as_float(u);
}
__device__ __forceinline__ void mma8(float& d0, float& d1, float& d2, float& d3,
                                     float a0, float a1, float a2, float a3,
                                     float b0, float b1) {
    asm("mma.sync.aligned.m16n8k8.row.col.f32.tf32.tf32.f32 "
        "{%0,%1,%2,%3}, {%4,%5,%6,%7}, {%8,%9}, {%0,%1,%2,%3};"
        : "+f"(d0), "+f"(d1), "+f"(d2), "+f"(d3)
        : "r"(__float_as_uint(a0)), "r"(__float_as_uint(a1)),
          "r"(__float_as_uint(a2)), "r"(__float_as_uint(a3)),
          "r"(__float_as_uint(b0)), "r"(__float_as_uint(b1)));
}
__device__ __forceinline__ unsigned smem_u32(const void* p) {
    return (unsigned)__cvta_generic_to_shared(p);
}
__device__ __forceinline__ void cp16(unsigned s, const void* g) {
    asm volatile("cp.async.cg.shared.global [%0], [%1], 16;" :: "r"(s), "l"(g));
}
__device__ __forceinline__ void cp_commit() { asm volatile("cp.async.commit_group;"); }
__device__ __forceinline__ void cp_wait1()  { asm volatile("cp.async.wait_group 1;"); }
__device__ __forceinline__ void cp_wait0()  { asm volatile("cp.async.wait_group 0;"); }

// ---------------------------------------------------------------------------
// Kernel 0: per-channel recurrence parameters
// ---------------------------------------------------------------------------
__global__ void params_kernel(const float* __restrict__ nu_log,
                              const float* __restrict__ theta_log) {
    int h = threadIdx.x;
    if (h < HID) {
        float mag = expf(-expf(nu_log[h]));
        float th  = expf(theta_log[h]);
        g_mag[h] = mag;
        g_th[h]  = th;
        g_lam_re[h] = mag * cosf(th);
        g_lam_im[h] = mag * sinf(th);
        g_gamma[h]  = sqrtf(fmaxf(1.0f - mag * mag, 0.0f));
    }
}

// ---------------------------------------------------------------------------
// Prep: weight fragments in mma order. element (K8, mt, lane, j):
//   g = lane>>2, tig = lane&3
//   m = mt*16 + g + (j&1)*8 ; k = K8*8 + tig + (j>>1)*4
// ---------------------------------------------------------------------------
#define WF1_N (16 * 32 * 32 * 4)   // 65536 frags * 4 = 262144 floats
#define WF2_N (80 * 8 * 32 * 4)    // 81920 floats
__global__ __launch_bounds__(256)
void prep_w_kernel(const float* __restrict__ Bre, const float* __restrict__ Bim,
                   const float* __restrict__ Cre, const float* __restrict__ Cim,
                   const float* __restrict__ Dm) {
    int idx = blockIdx.x * 256 + threadIdx.x;
    if (idx < WF1_N) {
        int j = idx & 3, lane = (idx >> 2) & 31, mt = (idx >> 7) & 31, K8 = idx >> 12;
        int g = lane >> 2, tig = lane & 3;
        int m = mt * 16 + g + (j & 1) * 8;
        int i = K8 * 8 + tig + (j >> 1) * 4;
        float v;
        if (m < 256) v = g_gamma[m] * Bre[(size_t)m * INDIM + i];
        else         v = g_gamma[m - 256] * Bim[(size_t)(m - 256) * INDIM + i];
        g_wf1[idx] = to_tf32(v);
    } else if (idx < WF1_N + WF2_N) {
        int e = idx - WF1_N;
        int j = e & 3, lane = (e >> 2) & 31, mt = (e >> 7) & 7, K8 = e >> 10;
        int g = lane >> 2, tig = lane & 3;
        int o = mt * 16 + g + (j & 1) * 8;
        int k = K8 * 8 + tig + (j >> 1) * 4;
        float v;
        if (k < 256)      v =  Cre[(size_t)o * HID + k];
        else if (k < 512) v = -Cim[(size_t)o * HID + (k - 256)];
        else              v =  Dm[(size_t)o * INDIM + (k - 512)];
        g_wf2[e] = to_tf32(v);
    }
}

// ---------------------------------------------------------------------------
// Prep: transpose X -> g_xt[b][i][t] (tf32-rounded)
// ---------------------------------------------------------------------------
__global__ __launch_bounds__(256)
void prep_xt_kernel(const float* __restrict__ X) {
    __shared__ float tile[32][33];
    int b  = blockIdx.z;
    int t0 = blockIdx.x * 32;
    int i0 = blockIdx.y * 32;
    int tid = threadIdx.x;
#pragma unroll
    for (int r = 0; r < 4; r++) {
        int idx = tid + 256 * r;
        int tl = idx >> 5, il = idx & 31;
        tile[tl][il] = X[((size_t)b * TLEN + t0 + tl) * INDIM + i0 + il];
    }
    __syncthreads();
#pragma unroll
    for (int r = 0; r < 4; r++) {
        int idx = tid + 256 * r;
        int il = idx >> 5, tl = idx & 31;
        g_xt[((size_t)b * INDIM + i0 + il) * TLEN + t0 + tl] = to_tf32(tile[tl][il]);
    }
}

// ---------------------------------------------------------------------------
// fill: t-data chunk (KC=32 rows x 128 t) into Bs[buf]
// ---------------------------------------------------------------------------
__device__ __forceinline__ void fill_b(float* Bs, int buf, const float* arow,
                                       int row, int cq) {
    unsigned sb = smem_u32(&Bs[buf * BBUF + row * PITCH]);
#pragma unroll
    for (int r = 0; r < 4; r++) {
        int c = cq + 8 * r;
        cp16(sb + 16 * c, arow + 4 * c);
    }
}
// fill: weight-fragment chunk (1024 float4) into Wf[buf]
// wsrc: float4 base at (K8base, mt0); k8stride: float4s per K8 step
__device__ __forceinline__ void fill_w(float* Wf, int buf, const float4* wsrc,
                                       int k8stride, int tid) {
    unsigned sw = smem_u32(&Wf[buf * WBUF]);
#pragma unroll
    for (int r = 0; r < 4; r++) {
        int fidx = tid + r * 256;
        int k8l = fidx >> 8, rem = fidx & 255;
        cp16(sw + 16 * fidx, wsrc + k8l * k8stride + rem);
    }
}

// ---------------------------------------------------------------------------
// compute one KC=32 chunk: A = weight frags (LDS.128), B = t rows
// ---------------------------------------------------------------------------
__device__ __forceinline__ void compute_chunk(const float* Bs, const float* Wf,
                                              int buf, int warp_m, int warp_n,
                                              int lane, int g, int tig,
                                              float acc[4][4][4]) {
    const float4* Wf4 = (const float4*)&Wf[buf * WBUF];
    const float*  Bsb = &Bs[buf * BBUF];
#pragma unroll
    for (int ks = 0; ks < 4; ks++) {
        float4 a[4];
#pragma unroll
        for (int mi = 0; mi < 4; mi++)
            a[mi] = Wf4[(ks * 8 + warp_m * 4 + mi) * 32 + lane];
        float b0[4], b1[4];
#pragma unroll
        for (int ni = 0; ni < 4; ni++) {
            int tw = warp_n * 32 + ni * 8 + g;
            b0[ni] = Bsb[(ks * 8 + tig) * PITCH + tw];
            b1[ni] = Bsb[(ks * 8 + tig + 4) * PITCH + tw];
        }
#pragma unroll
        for (int mi = 0; mi < 4; mi++)
#pragma unroll
            for (int ni = 0; ni < 4; ni++)
                mma8(acc[mi][ni][0], acc[mi][ni][1], acc[mi][ni][2], acc[mi][ni][3],
                     a[mi].x, a[mi].y, a[mi].z, a[mi].w, b0[ni], b1[ni]);
    }
}

// ---------------------------------------------------------------------------
// GEMM1: out[m=n(512)][t] = sum_i Wg1[m][i] * Xt[i][t]
// CTA: 128 m x 128 t; 8 warps (2 warp_m x 4 warp_n), warp m64 x n32.
// ---------------------------------------------------------------------------
__global__ __launch_bounds__(256)
void gemm1_kernel() {
    extern __shared__ float smem[];
    float* Bs = smem;
    float* Wf = smem + 2 * BBUF;

    int tid = threadIdx.x, lane = tid & 31, wid = tid >> 5;
    int warp_m = wid >> 2, warp_n = wid & 3;
    int g = lane >> 2, tig = lane & 3;
    int b = blockIdx.z, t0 = blockIdx.x * 128, m0 = blockIdx.y * 128;
    int mt0 = blockIdx.y * 8;

    float acc[4][4][4];
#pragma unroll
    for (int mi = 0; mi < 4; mi++)
#pragma unroll
        for (int ni = 0; ni < 4; ni++)
#pragma unroll
            for (int q = 0; q < 4; q++) acc[mi][ni][q] = 0.f;

    const int row = tid >> 3, cq = tid & 7;
    const int NCH = INDIM / KC;   // 4
    const float4* wbase = (const float4*)g_wf1;

    {
        const float* arow = g_xt + ((size_t)b * INDIM + row) * TLEN + t0;
        fill_b(Bs, 0, arow, row, cq);
        fill_w(Wf, 0, wbase + (size_t)(0 * 32 + mt0) * 32, 32 * 32, tid);
        cp_commit();
    }

    for (int c = 0; c < NCH; c++) {
        if (c + 1 < NCH) {
            int k = (c + 1) * KC + row;
            const float* arow = g_xt + ((size_t)b * INDIM + k) * TLEN + t0;
            fill_b(Bs, (c + 1) & 1, arow, row, cq);
            fill_w(Wf, (c + 1) & 1, wbase + (size_t)(((c + 1) * 4) * 32 + mt0) * 32, 32 * 32, tid);
            cp_commit();
            cp_wait1();
        } else {
            cp_wait0();
        }
        __syncthreads();
        compute_chunk(Bs, Wf, c & 1, warp_m, warp_n, lane, g, tig, acc);
        __syncthreads();
    }

    // epilogue: C row = weight index m (h, re/im uniform per CTA), col = t
    float* dst = (m0 < 256) ? g_bx_re : g_bx_im;
    int hbase = m0 & 255;
#pragma unroll
    for (int mi = 0; mi < 4; mi++) {
        int h = hbase + warp_m * 64 + mi * 16 + g;
#pragma unroll
        for (int ni = 0; ni < 4; ni++) {
            int t = t0 + warp_n * 32 + ni * 8 + 2 * tig;
            *(float2*)&dst[((size_t)b * HID + h) * TLEN + t] =
                make_float2(acc[mi][ni][0], acc[mi][ni][1]);
            *(float2*)&dst[((size_t)b * HID + h + 8) * TLEN + t] =
                make_float2(acc[mi][ni][2], acc[mi][ni][3]);
        }
    }
}

// ---------------------------------------------------------------------------
// Scan: inclusive complex scan over t, 8 elems/lane, prefetched, in place.
// ---------------------------------------------------------------------------
__global__ __launch_bounds__(256)
void scan_kernel() {
    int wg   = (blockIdx.x * blockDim.x + threadIdx.x) >> 5;
    int lane = threadIdx.x & 31;
    if (wg >= BATCH * HID) return;
    int b = wg >> 8;
    int h = wg & (HID - 1);

    float lr[8], li[8];
    lr[0] = g_lam_re[h]; li[0] = g_lam_im[h];
#pragma unroll
    for (int k = 1; k < 8; k++) {
        lr[k] = lr[k-1] * lr[0] - li[k-1] * li[0];
        li[k] = lr[k-1] * li[0] + li[k-1] * lr[0];
    }
    float pdr[5], pdi[5];
    pdr[0] = lr[7]; pdi[0] = li[7];
#pragma unroll
    for (int s = 1; s < 5; s++) {
        pdr[s] = pdr[s-1] * pdr[s-1] - pdi[s-1] * pdi[s-1];
        pdi[s] = 2.f * pdr[s-1] * pdi[s-1];
    }
    float mag = g_mag[h], th = g_th[h];
    float mp  = powf(mag, 8.f * (float)lane);
    float sa, ca;
    sincosf(th * 8.f * (float)lane, &sa, &ca);
    float c8r = mp * ca, c8i = mp * sa;

    float ccr = 0.f, cci = 0.f;
    size_t base = ((size_t)b * HID + h) * TLEN;
    const int NCH = TLEN / 256;

    size_t off = base + (size_t)lane * 8;
    float4 nr0 = *(const float4*)&g_bx_re[off];
    float4 nr1 = *(const float4*)&g_bx_re[off + 4];
    float4 ni0 = *(const float4*)&g_bx_im[off];
    float4 ni1 = *(const float4*)&g_bx_im[off + 4];

    for (int c = 0; c < NCH; c++) {
        float xr[8] = {nr0.x, nr0.y, nr0.z, nr0.w, nr1.x, nr1.y, nr1.z, nr1.w};
        float xi[8] = {ni0.x, ni0.y, ni0.z, ni0.w, ni1.x, ni1.y, ni1.z, ni1.w};
        size_t coff = off;
        if (c + 1 < NCH) {
            off += 256;
            nr0 = *(const float4*)&g_bx_re[off];
            nr1 = *(const float4*)&g_bx_re[off + 4];
            ni0 = *(const float4*)&g_bx_im[off];
            ni1 = *(const float4*)&g_bx_im[off + 4];
        }

        float yr[8], yi[8];
        yr[0] = xr[0]; yi[0] = xi[0];
#pragma unroll
        for (int k = 1; k < 8; k++) {
            yr[k] = xr[k] + lr[0] * yr[k-1] - li[0] * yi[k-1];
            yi[k] = xi[k] + lr[0] * yi[k-1] + li[0] * yr[k-1];
        }

        float sr = yr[7], si = yi[7];
#pragma unroll
        for (int s = 0; s < 5; s++) {
            int d = 1 << s;
            float tr = __shfl_up_sync(0xffffffffu, sr, d);
            float ti = __shfl_up_sync(0xffffffffu, si, d);
            if (lane >= d) {
                sr += pdr[s] * tr - pdi[s] * ti;
                si += pdr[s] * ti + pdi[s] * tr;
            }
        }
        float qr = __shfl_up_sync(0xffffffffu, sr, 1);
        float qi = __shfl_up_sync(0xffffffffu, si, 1);
        if (lane == 0) { qr = 0.f; qi = 0.f; }
        qr += c8r * ccr - c8i * cci;
        qi += c8r * cci + c8i * ccr;

        float or_[8], oi_[8];
#pragma unroll
        for (int k = 0; k < 8; k++) {
            or_[k] = yr[k] + lr[k] * qr - li[k] * qi;
            oi_[k] = yi[k] + lr[k] * qi + li[k] * qr;
        }

        ccr = __shfl_sync(0xffffffffu, or_[7], 31);
        cci = __shfl_sync(0xffffffffu, oi_[7], 31);

        *(float4*)&g_bx_re[coff]     = make_float4(to_tf32(or_[0]), to_tf32(or_[1]), to_tf32(or_[2]), to_tf32(or_[3]));
        *(float4*)&g_bx_re[coff + 4] = make_float4(to_tf32(or_[4]), to_tf32(or_[5]), to_tf32(or_[6]), to_tf32(or_[7]));
        *(float4*)&g_bx_im[coff]     = make_float4(to_tf32(oi_[0]), to_tf32(oi_[1]), to_tf32(oi_[2]), to_tf32(oi_[3]));
        *(float4*)&g_bx_im[coff + 4] = make_float4(to_tf32(oi_[4]), to_tf32(oi_[5]), to_tf32(oi_[6]), to_tf32(oi_[7]));
    }
}

// ---------------------------------------------------------------------------
// GEMM2: Y[t][o] = sum_{k<640} Wt2[o][k] * A[k][t]
// CTA: 128 o x 128 t; weight frags cover all M=128 (mt0=0).
// ---------------------------------------------------------------------------
__global__ __launch_bounds__(256)
void gemm2_kernel(float* __restrict__ Y) {
    extern __shared__ float smem[];
    float* Bs = smem;
    float* Wf = smem + 2 * BBUF;

    int tid = threadIdx.x, lane = tid & 31, wid = tid >> 5;
    int warp_m = wid >> 2, warp_n = wid & 3;
    int g = lane >> 2, tig = lane & 3;
    int b = blockIdx.y, t0 = blockIdx.x * 128;

    float acc[4][4][4];
#pragma unroll
    for (int mi = 0; mi < 4; mi++)
#pragma unroll
        for (int ni = 0; ni < 4; ni++)
#pragma unroll
            for (int q = 0; q < 4; q++) acc[mi][ni][q] = 0.f;

    const int row = tid >> 3, cq = tid & 7;
    const int NCH = 640 / KC;   // 20
    const float4* wbase = (const float4*)g_wf2;

    auto arow_of = [&](int k) -> const float* {
        if (k < 256)      return g_bx_re + ((size_t)b * HID + k) * TLEN + t0;
        else if (k < 512) return g_bx_im + ((size_t)b * HID + (k - 256)) * TLEN + t0;
        else              return g_xt   + ((size_t)b * INDIM + (k - 512)) * TLEN + t0;
    };

    {
        fill_b(Bs, 0, arow_of(row), row, cq);
        fill_w(Wf, 0, wbase, 8 * 32, tid);   // chunk 0: K8 0..3, contiguous
        cp_commit();
    }

    for (int c = 0; c < NCH; c++) {
        if (c + 1 < NCH) {
            int k = (c + 1) * KC + row;
            fill_b(Bs, (c + 1) & 1, arow_of(k), row, cq);
            fill_w(Wf, (c + 1) & 1, wbase + (size_t)((c + 1) * 4) * 256, 8 * 32, tid);
            cp_commit();
            cp_wait1();
        } else {
            cp_wait0();
        }
        __syncthreads();
        compute_chunk(Bs, Wf, c & 1, warp_m, warp_n, lane, g, tig, acc);
        __syncthreads();
    }

    // epilogue: C row = o, col = t; Y[b][t][o]
#pragma unroll
    for (int mi = 0; mi < 4; mi++) {
        int o = warp_m * 64 + mi * 16 + g;
#pragma unroll
        for (int ni = 0; ni < 4; ni++) {
            int t = t0 + warp_n * 32 + ni * 8 + 2 * tig;
            size_t y0 = ((size_t)b * TLEN + t) * OUTDIM;
            size_t y1 = ((size_t)b * TLEN + t + 1) * OUTDIM;
            Y[y0 + o]     = acc[mi][ni][0];
            Y[y1 + o]     = acc[mi][ni][1];
            Y[y0 + o + 8] = acc[mi][ni][2];
            Y[y1 + o + 8] = acc[mi][ni][3];
        }
    }
}

// ---------------------------------------------------------------------------
extern "C" void kernel_launch(void* const* d_in, const int* in_sizes, int n_in,
                              void* d_out, int out_size) {
    const float* X         = (const float*)d_in[0];
    const float* nu_log    = (const float*)d_in[1];
    const float* theta_log = (const float*)d_in[2];
    const float* B_re      = (const float*)d_in[3];
    const float* B_im      = (const float*)d_in[4];
    const float* C_re      = (const float*)d_in[5];
    const float* C_im      = (const float*)d_in[6];
    const float* D         = (const float*)d_in[7];
    float* Y = (float*)d_out;

    cudaFuncSetAttribute(gemm1_kernel, cudaFuncAttributeMaxDynamicSharedMemorySize, SMEM_BYTES);
    cudaFuncSetAttribute(gemm2_kernel, cudaFuncAttributeMaxDynamicSharedMemorySize, SMEM_BYTES);

    params_kernel<<<1, 256>>>(nu_log, theta_log);

    int prep_total = WF1_N + WF2_N;
    prep_w_kernel<<<(prep_total + 255) / 256, 256>>>(B_re, B_im, C_re, C_im, D);

    dim3 gxt(TLEN / 32, INDIM / 32, BATCH);
    prep_xt_kernel<<<gxt, 256>>>(X);

    dim3 g1(TLEN / 128, 4, BATCH);
    gemm1_kernel<<<g1, 256, SMEM_BYTES>>>();

    scan_kernel<<<(BATCH * HID * 32) / 256, 256>>>();

    dim3 g2(TLEN / 128, BATCH);
    gemm2_kernel<<<g2, 256, SMEM_BYTES>>>(Y);
}